// round 11
// baseline (speedup 1.0000x reference)
#include <cuda_runtime.h>
#include <math.h>

// Problem constants
#define S_LEN  2048
#define BATCH  2
#define EMB    768
#define NHEAD  12
#define HD     64
#define NH     (BATCH*NHEAD)        // 24 flattened heads
#define M_ROWS (S_LEN*BATCH)        // 4096
#define OUT0   (S_LEN*BATCH*EMB)    // 3145728 floats (output tensor)

// ---------------- device scratch (static, allocation-free) ----------------
// g_Qh/g_Kh/g_Vh hold tf32-PREROUNDED values (bit pattern of cvt.rna.tf32).
__device__ float g_Qh[NH * S_LEN * HD];   // [head, s, d]
__device__ float g_Kh[NH * S_LEN * HD];
__device__ float g_Vh[NH * S_LEN * HD];
__device__ float g_ctx[M_ROWS * EMB];     // attn_output in [S,B,E] layout (full fp32)

// ============================================================================
// portable (compute_103-safe) helpers
// tf32 m16n8k8 fragment layouts (PTX ISA):
//  A (16x8):  a0=(g, t)  a1=(g+8, t)  a2=(g, t+4)  a3=(g+8, t+4)   [g=lane>>2, t=lane&3]
//  B (8x8):   b0=(k=t, n=g)  b1=(k=t+4, n=g)
//  C (16x8):  c0=(g, 2t) c1=(g, 2t+1) c2=(g+8, 2t) c3=(g+8, 2t+1)
// ============================================================================
__device__ __forceinline__ unsigned sm_addr(const void* p) {
    unsigned a;
    asm("{ .reg .u64 t; cvta.to.shared.u64 t, %1; cvt.u32.u64 %0, t; }" : "=r"(a) : "l"(p));
    return a;
}
__device__ __forceinline__ unsigned f2tf(float x) {
    unsigned r;
    asm("cvt.rna.tf32.f32 %0, %1;" : "=r"(r) : "f"(x));
    return r;
}
__device__ __forceinline__ float f2tf_f(float x) { return __uint_as_float(f2tf(x)); }

__device__ __forceinline__ void mma_tf(float c[4], unsigned a0, unsigned a1,
                                       unsigned a2, unsigned a3,
                                       unsigned b0, unsigned b1) {
    asm volatile(
        "mma.sync.aligned.m16n8k8.row.col.f32.tf32.tf32.f32 "
        "{%0,%1,%2,%3}, {%4,%5,%6,%7}, {%8,%9}, {%0,%1,%2,%3};"
        : "+f"(c[0]), "+f"(c[1]), "+f"(c[2]), "+f"(c[3])
        : "r"(a0), "r"(a1), "r"(a2), "r"(a3), "r"(b0), "r"(b1));
}
__device__ __forceinline__ void cpa16(unsigned saddr, const void* gptr) {
    asm volatile("cp.async.cg.shared.global [%0], [%1], 16;" :: "r"(saddr), "l"(gptr));
}
#define CP_COMMIT()  asm volatile("cp.async.commit_group;")
#define CP_WAIT0()   asm volatile("cp.async.wait_group 0;")
#define CP_WAIT1()   asm volatile("cp.async.wait_group 1;")

// ============================================================================
// Projection GEMM core: C[128x128] = A[128x768] @ B[128x768]^T (both K-major).
// 8 warps (2x4): warp tile 64m x 32n; K-chunks of 32, cp.async double-buffered.
// Each landed chunk is converted to tf32 bits IN SMEM (one vector pass), so the
// mma operand chains are pure LDS -> MMA (no F2FP in the critical path).
// ============================================================================
#define PLD 36
#define PROJ_SMEM (4 * 128 * PLD * 4)   // 73728 B

__device__ __forceinline__ void proj_core(const float* __restrict__ Ag,
                                          const float* __restrict__ Bg,
                                          float (&acc)[4][4][4], float* sh)
{
    float* Ab[2] = { sh,                 sh + 128 * PLD };
    float* Bb[2] = { sh + 2 * 128 * PLD, sh + 3 * 128 * PLD };
    const int tid = threadIdx.x;
    const int lane = tid & 31, wid = tid >> 5;
    const int g = lane >> 2, t = lane & 3;
    const int wy = wid >> 2, wx = wid & 3;

    auto stage = [&](int c, int bs) {
        #pragma unroll
        for (int i = 0; i < 4; i++) {
            int idx = tid + 256 * i;               // 0..1023 (float4 slots per tile)
            int row = idx >> 3, c4 = (idx & 7) * 4;
            cpa16(sm_addr(&Ab[bs][row * PLD + c4]), Ag + (size_t)row * EMB + c * 32 + c4);
            cpa16(sm_addr(&Bb[bs][row * PLD + c4]), Bg + (size_t)row * EMB + c * 32 + c4);
        }
        CP_COMMIT();
    };
    auto convert = [&](int bs) {                   // fp32 -> tf32 bits, in place
        #pragma unroll
        for (int i = 0; i < 4; i++) {              // 1024 slots; body does A and B
            int idx = tid + 256 * i;
            int row = idx >> 3, c4 = (idx & 7) * 4;
            float4* pa = (float4*)&Ab[bs][row * PLD + c4];
            float4 va = *pa;
            va.x = f2tf_f(va.x); va.y = f2tf_f(va.y);
            va.z = f2tf_f(va.z); va.w = f2tf_f(va.w);
            *pa = va;
            float4* pb = (float4*)&Bb[bs][row * PLD + c4];
            float4 vb = *pb;
            vb.x = f2tf_f(vb.x); vb.y = f2tf_f(vb.y);
            vb.z = f2tf_f(vb.z); vb.w = f2tf_f(vb.w);
            *pb = vb;
        }
    };

    stage(0, 0);
    for (int c = 0; c < 24; c++) {
        __syncthreads();                 // prev compute finished before overwrite
        if (c + 1 < 24) { stage(c + 1, (c + 1) & 1); CP_WAIT1(); }
        else           { CP_WAIT0(); }
        __syncthreads();                 // chunk c landed, visible
        convert(c & 1);
        __syncthreads();                 // converted bits visible

        const float* Af = Ab[c & 1];
        const float* Bf = Bb[c & 1];
        #pragma unroll
        for (int ks = 0; ks < 4; ks++) {
            const int k0s = 8 * ks;
            unsigned a[4][4];
            #pragma unroll
            for (int mt = 0; mt < 4; mt++) {
                int ra = (64 * wy + 16 * mt + g) * PLD + k0s;
                a[mt][0] = __float_as_uint(Af[ra + t]);
                a[mt][1] = __float_as_uint(Af[ra + 8 * PLD + t]);
                a[mt][2] = __float_as_uint(Af[ra + t + 4]);
                a[mt][3] = __float_as_uint(Af[ra + 8 * PLD + t + 4]);
            }
            #pragma unroll
            for (int nt = 0; nt < 4; nt++) {
                int rb = (32 * wx + 8 * nt + g) * PLD + k0s;
                unsigned b0 = __float_as_uint(Bf[rb + t]);
                unsigned b1 = __float_as_uint(Bf[rb + t + 4]);
                #pragma unroll
                for (int mt = 0; mt < 4; mt++)
                    mma_tf(acc[mt][nt], a[mt][0], a[mt][1], a[mt][2], a[mt][3], b0, b1);
            }
        }
    }
}

// ============================================================================
// Kernel A: fused QKV projection.  grid (32, 6, 3); split-head output.
// Stores tf32-prerounded (acc+bias) so flash needs no conversions at all.
// ============================================================================
__global__ __launch_bounds__(256, 2) void qkv_gemm(
    const float* __restrict__ q, const float* __restrict__ k, const float* __restrict__ v,
    const float* __restrict__ WQ, const float* __restrict__ WK, const float* __restrict__ WV,
    const float* __restrict__ bQ, const float* __restrict__ bK, const float* __restrict__ bV)
{
    extern __shared__ float sh[];
    const int m0 = blockIdx.x * 128, n0 = blockIdx.y * 128, sel = blockIdx.z;
    const float* X    = (sel == 0) ? q  : (sel == 1) ? k  : v;
    const float* W    = (sel == 0) ? WQ : (sel == 1) ? WK : WV;
    const float* bias = (sel == 0) ? bQ : (sel == 1) ? bK : bV;
    float* dst        = (sel == 0) ? g_Qh : (sel == 1) ? g_Kh : g_Vh;

    float acc[4][4][4] = {};
    proj_core(X + (size_t)m0 * EMB, W + (size_t)n0 * EMB, acc, sh);

    const int tid = threadIdx.x, lane = tid & 31, wid = tid >> 5;
    const int g = lane >> 2, t = lane & 3;
    const int wy = wid >> 2, wx = wid & 3;
    #pragma unroll
    for (int mt = 0; mt < 4; mt++) {
        #pragma unroll
        for (int nt = 0; nt < 4; nt++) {
            int n = n0 + 32 * wx + 8 * nt + 2 * t;
            int h = n >> 6, d0 = n & 63;
            float bb0 = bias[n], bb1 = bias[n + 1];
            int row = m0 + 64 * wy + 16 * mt + g;
            {
                int s = row >> 1, bI = row & 1;
                float2 st = make_float2(f2tf_f(acc[mt][nt][0] + bb0),
                                        f2tf_f(acc[mt][nt][1] + bb1));
                *(float2*)&dst[((size_t)(bI * NHEAD + h) * S_LEN + s) * HD + d0] = st;
            }
            {
                int r2 = row + 8;
                int s = r2 >> 1, bI = r2 & 1;
                float2 st = make_float2(f2tf_f(acc[mt][nt][2] + bb0),
                                        f2tf_f(acc[mt][nt][3] + bb1));
                *(float2*)&dst[((size_t)(bI * NHEAD + h) * S_LEN + s) * HD + d0] = st;
            }
        }
    }
}

// ============================================================================
// Kernel D: output projection (separate launch; 192 blocks, 2 CTA/SM).
// ============================================================================
__global__ __launch_bounds__(256, 2) void out_gemm(
    const float* __restrict__ W, const float* __restrict__ bias, float* __restrict__ out)
{
    extern __shared__ float sh[];
    const int m0 = blockIdx.x * 128, n0 = blockIdx.y * 128;

    float acc[4][4][4] = {};
    proj_core(g_ctx + (size_t)m0 * EMB, W + (size_t)n0 * EMB, acc, sh);

    const int tid = threadIdx.x, lane = tid & 31, wid = tid >> 5;
    const int g = lane >> 2, t = lane & 3;
    const int wy = wid >> 2, wx = wid & 3;
    #pragma unroll
    for (int mt = 0; mt < 4; mt++) {
        #pragma unroll
        for (int nt = 0; nt < 4; nt++) {
            int n = n0 + 32 * wx + 8 * nt + 2 * t;
            float bb0 = bias[n], bb1 = bias[n + 1];
            int row = m0 + 64 * wy + 16 * mt + g;
            *(float2*)&out[(size_t)row * EMB + n] =
                make_float2(acc[mt][nt][0] + bb0, acc[mt][nt][1] + bb1);
            *(float2*)&out[(size_t)(row + 8) * EMB + n] =
                make_float2(acc[mt][nt][2] + bb0, acc[mt][nt][3] + bb1);
        }
    }
}

// ============================================================================
// Kernel B: flash attention + fused softmax-normalize tail.
// grid (16, 24), 256 thr, 2 CTA/SM.  Inputs tf32-prerounded.
// Main loop: warp w owns q-rows [16w,16w+16); raw scores streamed to wraw.
// Tail: block re-reads ITS OWN 128x2048 wraw slab and normalizes in place
// using m/l parked in smem (reuses Ps area) — overlaps other blocks' compute.
// Pads: Q/K/P = 68, V = 72 (conflict-free for their access patterns).
// ============================================================================
#define QPAD 68
#define KPAD 68
#define VPAD 72
#define PPAD 68
#define FLASH_SMEM ((128*QPAD + 64*KPAD + 64*VPAD + 128*PPAD) * 4)   // 105472 B

__global__ __launch_bounds__(256, 2) void flash_tc(float* __restrict__ wraw)
{
    extern __shared__ float sh[];
    float* Qs = sh;                          // [128][QPAD] tf32 bits
    float* Ks = Qs + 128 * QPAD;             // [64][KPAD]  tf32 bits
    float* Vs = Ks + 64 * KPAD;              // [64][VPAD]  tf32 bits
    float* Ps = Vs + 64 * VPAD;              // [128][PPAD] per-warp P tiles
    float* sm_m = Ps;                        // tail reuse: [128] row maxes
    float* sm_l = Ps + 128;                  // tail reuse: [128] row sums

    const int tid = threadIdx.x, lane = tid & 31, wid = tid >> 5;
    const int g = lane >> 2, t = lane & 3;
    const int hn = blockIdx.y;               // flattened head
    const int q0 = blockIdx.x * 128;

    const float* Qb = g_Qh + ((size_t)hn * S_LEN + q0) * HD;
    const float* Kb = g_Kh + (size_t)hn * S_LEN * HD;
    const float* Vb = g_Vh + (size_t)hn * S_LEN * HD;

    // preamble: stage Q, K0, V0 (already tf32 bits in gmem)
    #pragma unroll
    for (int i = 0; i < 8; i++) {
        int idx = tid + 256 * i; int row = idx >> 4, c4 = (idx & 15) * 4;
        cpa16(sm_addr(&Qs[row * QPAD + c4]), Qb + (size_t)row * HD + c4);
    }
    #pragma unroll
    for (int i = 0; i < 4; i++) {
        int idx = tid + 256 * i; int row = idx >> 4, c4 = (idx & 15) * 4;
        cpa16(sm_addr(&Ks[row * KPAD + c4]), Kb + (size_t)row * HD + c4);
        cpa16(sm_addr(&Vs[row * VPAD + c4]), Vb + (size_t)row * HD + c4);
    }
    CP_COMMIT();
    CP_WAIT0();

    float m0 = -INFINITY, m1 = -INFINITY, l0 = 0.f, l1 = 0.f;
    float oa[8][4] = {};
    const int qr = 16 * wid + g;             // warp-local base row (second = qr+8)
    float* Pw = Ps + wid * 16 * PPAD;        // per-warp P tile

    for (int kt = 0; kt < 32; kt++) {
        __syncthreads();                     // kt=0: preamble visible; kt>0: tail pair
        if (kt) { CP_WAIT0(); __syncthreads(); }   // K(kt), V(kt) landed + visible

        // ---- S = Q @ K^T / 8 ----
        float sa[8][4] = {};
        #pragma unroll
        for (int k8 = 0; k8 < 8; k8++) {
            int ra = qr * QPAD + 8 * k8;
            unsigned a0 = __float_as_uint(Qs[ra + t]);
            unsigned a1 = __float_as_uint(Qs[ra + 8 * QPAD + t]);
            unsigned a2 = __float_as_uint(Qs[ra + t + 4]);
            unsigned a3 = __float_as_uint(Qs[ra + 8 * QPAD + t + 4]);
            #pragma unroll
            for (int nt = 0; nt < 8; nt++) {
                int rb = (8 * nt + g) * KPAD + 8 * k8;
                mma_tf(sa[nt], a0, a1, a2, a3,
                       __float_as_uint(Ks[rb + t]),
                       __float_as_uint(Ks[rb + t + 4]));
            }
        }
        #pragma unroll
        for (int nt = 0; nt < 8; nt++) {
            sa[nt][0] *= 0.125f; sa[nt][1] *= 0.125f;
            sa[nt][2] *= 0.125f; sa[nt][3] *= 0.125f;
        }

        __syncthreads();                     // all warps done reading Ks
        if (kt < 31) {                       // prefetch K(kt+1) under softmax+PV
            #pragma unroll
            for (int i = 0; i < 4; i++) {
                int idx = tid + 256 * i; int row = idx >> 4, c4 = (idx & 15) * 4;
                cpa16(sm_addr(&Ks[row * KPAD + c4]),
                      Kb + (size_t)((kt + 1) * 64 + row) * HD + c4);
            }
            CP_COMMIT();
        }

        // ---- raw scores -> weights region (C layout: cols 2t,2t+1) ----
        if (wraw) {
            size_t rb0 = ((size_t)hn * S_LEN + (q0 + qr)) * S_LEN + (size_t)kt * 64 + 2 * t;
            #pragma unroll
            for (int nt = 0; nt < 8; nt++) {
                *(float2*)&wraw[rb0 + 8 * nt] = make_float2(sa[nt][0], sa[nt][1]);
                *(float2*)&wraw[rb0 + 8 * nt + 8 * (size_t)S_LEN] =
                    make_float2(sa[nt][2], sa[nt][3]);
            }
        }

        // ---- online softmax (row qr via c0/c1, row qr+8 via c2/c3) ----
        float lm0 = -INFINITY, lm1 = -INFINITY;
        #pragma unroll
        for (int nt = 0; nt < 8; nt++) {
            lm0 = fmaxf(lm0, fmaxf(sa[nt][0], sa[nt][1]));
            lm1 = fmaxf(lm1, fmaxf(sa[nt][2], sa[nt][3]));
        }
        lm0 = fmaxf(lm0, __shfl_xor_sync(0xffffffffu, lm0, 1));
        lm0 = fmaxf(lm0, __shfl_xor_sync(0xffffffffu, lm0, 2));
        lm1 = fmaxf(lm1, __shfl_xor_sync(0xffffffffu, lm1, 1));
        lm1 = fmaxf(lm1, __shfl_xor_sync(0xffffffffu, lm1, 2));
        float nm0 = fmaxf(m0, lm0), nm1 = fmaxf(m1, lm1);
        float ts0 = 0.f, ts1 = 0.f;
        #pragma unroll
        for (int nt = 0; nt < 8; nt++) {
            float p0 = __expf(sa[nt][0] - nm0);
            float p1 = __expf(sa[nt][1] - nm0);
            float p2 = __expf(sa[nt][2] - nm1);
            float p3 = __expf(sa[nt][3] - nm1);
            ts0 += p0 + p1; ts1 += p2 + p3;
            sa[nt][0] = f2tf_f(p0);          // tf32 bits, C layout
            sa[nt][1] = f2tf_f(p1);
            sa[nt][2] = f2tf_f(p2);
            sa[nt][3] = f2tf_f(p3);
        }
        ts0 += __shfl_xor_sync(0xffffffffu, ts0, 1);
        ts0 += __shfl_xor_sync(0xffffffffu, ts0, 2);
        ts1 += __shfl_xor_sync(0xffffffffu, ts1, 1);
        ts1 += __shfl_xor_sync(0xffffffffu, ts1, 2);
        float sc0 = __expf(m0 - nm0), sc1 = __expf(m1 - nm1);
        l0 = l0 * sc0 + ts0; l1 = l1 * sc1 + ts1;
        m0 = nm0; m1 = nm1;
        #pragma unroll
        for (int nt = 0; nt < 8; nt++) {
            oa[nt][0] *= sc0; oa[nt][1] *= sc0;
            oa[nt][2] *= sc1; oa[nt][3] *= sc1;
        }

        // ---- P: C-layout store to per-warp tile, A-layout reload ----
        #pragma unroll
        for (int nt = 0; nt < 8; nt++) {
            *(float2*)&Pw[g * PPAD + 8 * nt + 2 * t] =
                make_float2(sa[nt][0], sa[nt][1]);
            *(float2*)&Pw[(g + 8) * PPAD + 8 * nt + 2 * t] =
                make_float2(sa[nt][2], sa[nt][3]);
        }
        __syncwarp();

        // ---- O += P @ V ----
        #pragma unroll
        for (int k8 = 0; k8 < 8; k8++) {
            int pa = g * PPAD + 8 * k8;
            unsigned a0 = __float_as_uint(Pw[pa + t]);
            unsigned a1 = __float_as_uint(Pw[pa + 8 * PPAD + t]);
            unsigned a2 = __float_as_uint(Pw[pa + t + 4]);
            unsigned a3 = __float_as_uint(Pw[pa + t + 4 + 8 * PPAD]);
            #pragma unroll
            for (int nt = 0; nt < 8; nt++) {
                int vb = (8 * k8 + t) * VPAD + 8 * nt + g;
                mma_tf(oa[nt], a0, a1, a2, a3,
                       __float_as_uint(Vs[vb]),
                       __float_as_uint(Vs[vb + 4 * VPAD]));
            }
        }
        __syncthreads();                     // all warps done reading Vs
        if (kt < 31) {                       // prefetch V(kt+1)
            #pragma unroll
            for (int i = 0; i < 4; i++) {
                int idx = tid + 256 * i; int row = idx >> 4, c4 = (idx & 15) * 4;
                cpa16(sm_addr(&Vs[row * VPAD + c4]),
                      Vb + (size_t)((kt + 1) * 64 + row) * HD + c4);
            }
            CP_COMMIT();
        }
    }

    // ---- attention-output epilogue: normalize, scatter ctx to [S,B,E] ----
    float inv0 = 1.f / l0, inv1 = 1.f / l1;
    const int r0 = q0 + qr, r1 = r0 + 8;
    const int bI = hn / NHEAD, hI = hn % NHEAD;
    #pragma unroll
    for (int nt = 0; nt < 8; nt++) {
        int d0 = 8 * nt + 2 * t;
        *(float2*)&g_ctx[((size_t)r0 * BATCH + bI) * EMB + hI * HD + d0] =
            make_float2(oa[nt][0] * inv0, oa[nt][1] * inv0);
        *(float2*)&g_ctx[((size_t)r1 * BATCH + bI) * EMB + hI * HD + d0] =
            make_float2(oa[nt][2] * inv1, oa[nt][3] * inv1);
    }

    // ---- fused softmax-normalize tail over this block's own wraw slab ----
    if (wraw) {
        __syncthreads();                     // Ps reads done -> safe to reuse as m/l
        // park m/l in smem at LOCAL row index (qr is already block-local, 0..127)
        if (t == 0) {
            sm_m[qr]     = m0;  sm_l[qr]     = l0;
            sm_m[qr + 8] = m1;  sm_l[qr + 8] = l1;
        }
        __syncthreads();                     // m/l visible; also orders our wraw stores

        float* slab = wraw + (size_t)hn * S_LEN * S_LEN + (size_t)q0 * S_LEN;
        // 128 rows x 2048 cols = 65536 float4; 256 threads x 256 iters
        for (int j = 0; j < 256; j++) {
            int i4 = j * 256 + tid;
            int row = i4 >> 9;               // 512 float4 per row
            float m = sm_m[row];
            float inv = 1.f / sm_l[row];
            float4* wv = (float4*)slab + i4;
            float4 vv = *wv;
            vv.x = __expf(vv.x - m) * inv;
            vv.y = __expf(vv.y - m) * inv;
            vv.z = __expf(vv.z - m) * inv;
            vv.w = __expf(vv.w - m) * inv;
            *wv = vv;
        }
    }
}

// ============================================================================
extern "C" void kernel_launch(void* const* d_in, const int* in_sizes, int n_in,
                              void* d_out, int out_size)
{
    const float* q   = (const float*)d_in[0];
    const float* k   = (const float*)d_in[1];
    const float* v   = (const float*)d_in[2];
    const float* W_Q = (const float*)d_in[3];
    const float* W_K = (const float*)d_in[4];
    const float* W_V = (const float*)d_in[5];
    const float* b_Q = (const float*)d_in[6];
    const float* b_K = (const float*)d_in[7];
    const float* b_V = (const float*)d_in[8];
    const float* W_O = (const float*)d_in[9];
    const float* b_O = (const float*)d_in[10];
    float* out = (float*)d_out;

    const long long NW_LL = (long long)NH * S_LEN * S_LEN;  // 100663296
    const long long total = (long long)OUT0 + NW_LL;
    float* wraw = ((long long)out_size >= total) ? (out + OUT0) : nullptr;

    cudaFuncSetAttribute(qkv_gemm,
                         cudaFuncAttributeMaxDynamicSharedMemorySize, PROJ_SMEM);
    cudaFuncSetAttribute(out_gemm,
                         cudaFuncAttributeMaxDynamicSharedMemorySize, PROJ_SMEM);
    cudaFuncSetAttribute(flash_tc,
                         cudaFuncAttributeMaxDynamicSharedMemorySize, FLASH_SMEM);

    dim3 gQKV(M_ROWS / 128, EMB / 128, 3);   // 32 x 6 x 3
    qkv_gemm<<<gQKV, 256, PROJ_SMEM>>>(q, k, v, W_Q, W_K, W_V, b_Q, b_K, b_V);

    dim3 gB(S_LEN / 128, NH);                // 16 x 24
    flash_tc<<<gB, 256, FLASH_SMEM>>>(wraw);

    dim3 gO(M_ROWS / 128, EMB / 128);        // 32 x 6
    out_gemm<<<gO, 256, PROJ_SMEM>>>(W_O, b_O, out);
}

// round 12
// speedup vs baseline: 1.1831x; 1.1831x over previous
#include <cuda_runtime.h>
#include <math.h>

// Problem constants
#define S_LEN  2048
#define BATCH  2
#define EMB    768
#define NHEAD  12
#define HD     64
#define NH     (BATCH*NHEAD)        // 24 flattened heads
#define M_ROWS (S_LEN*BATCH)        // 4096
#define OUT0   (S_LEN*BATCH*EMB)    // 3145728 floats (output tensor)

// ---------------- device scratch (static, allocation-free) ----------------
// g_Qh/g_Kh/g_Vh hold tf32-PREROUNDED values (bit pattern of cvt.rna.tf32).
__device__ float g_Qh[NH * S_LEN * HD];   // [head, s, d]
__device__ float g_Kh[NH * S_LEN * HD];
__device__ float g_Vh[NH * S_LEN * HD];
__device__ float g_ctx[M_ROWS * EMB];     // attn_output in [S,B,E] layout (full fp32)
__device__ float g_m[NH * S_LEN];         // per-row softmax max
__device__ float g_l[NH * S_LEN];         // per-row softmax sum

// ============================================================================
// portable (compute_103-safe) helpers
// tf32 m16n8k8 fragment layouts (PTX ISA):
//  A (16x8):  a0=(g, t)  a1=(g+8, t)  a2=(g, t+4)  a3=(g+8, t+4)   [g=lane>>2, t=lane&3]
//  B (8x8):   b0=(k=t, n=g)  b1=(k=t+4, n=g)
//  C (16x8):  c0=(g, 2t) c1=(g, 2t+1) c2=(g+8, 2t) c3=(g+8, 2t+1)
// ============================================================================
__device__ __forceinline__ unsigned sm_addr(const void* p) {
    unsigned a;
    asm("{ .reg .u64 t; cvta.to.shared.u64 t, %1; cvt.u32.u64 %0, t; }" : "=r"(a) : "l"(p));
    return a;
}
__device__ __forceinline__ unsigned f2tf(float x) {
    unsigned r;
    asm("cvt.rna.tf32.f32 %0, %1;" : "=r"(r) : "f"(x));
    return r;
}
__device__ __forceinline__ float f2tf_f(float x) { return __uint_as_float(f2tf(x)); }

__device__ __forceinline__ void mma_tf(float c[4], unsigned a0, unsigned a1,
                                       unsigned a2, unsigned a3,
                                       unsigned b0, unsigned b1) {
    asm volatile(
        "mma.sync.aligned.m16n8k8.row.col.f32.tf32.tf32.f32 "
        "{%0,%1,%2,%3}, {%4,%5,%6,%7}, {%8,%9}, {%0,%1,%2,%3};"
        : "+f"(c[0]), "+f"(c[1]), "+f"(c[2]), "+f"(c[3])
        : "r"(a0), "r"(a1), "r"(a2), "r"(a3), "r"(b0), "r"(b1));
}
__device__ __forceinline__ void cpa16(unsigned saddr, const void* gptr) {
    asm volatile("cp.async.cg.shared.global [%0], [%1], 16;" :: "r"(saddr), "l"(gptr));
}
#define CP_COMMIT()  asm volatile("cp.async.commit_group;")
#define CP_WAIT0()   asm volatile("cp.async.wait_group 0;")
#define CP_WAIT1()   asm volatile("cp.async.wait_group 1;")

// ============================================================================
// Projection GEMM core: C[128x128] = A[128x768] @ B[128x768]^T (both K-major).
// 8 warps (2x4): warp tile 64m x 32n; K-chunks of 32, cp.async double-buffered.
// Each landed chunk is converted to tf32 bits IN SMEM (one vector pass), so the
// mma operand chains are pure LDS -> MMA (no F2FP in the critical path).
// ============================================================================
#define PLD 36
#define PROJ_SMEM (4 * 128 * PLD * 4)   // 73728 B

__device__ __forceinline__ void proj_core(const float* __restrict__ Ag,
                                          const float* __restrict__ Bg,
                                          float (&acc)[4][4][4], float* sh)
{
    float* Ab[2] = { sh,                 sh + 128 * PLD };
    float* Bb[2] = { sh + 2 * 128 * PLD, sh + 3 * 128 * PLD };
    const int tid = threadIdx.x;
    const int lane = tid & 31, wid = tid >> 5;
    const int g = lane >> 2, t = lane & 3;
    const int wy = wid >> 2, wx = wid & 3;

    auto stage = [&](int c, int bs) {
        #pragma unroll
        for (int i = 0; i < 4; i++) {
            int idx = tid + 256 * i;               // 0..1023 (float4 slots per tile)
            int row = idx >> 3, c4 = (idx & 7) * 4;
            cpa16(sm_addr(&Ab[bs][row * PLD + c4]), Ag + (size_t)row * EMB + c * 32 + c4);
            cpa16(sm_addr(&Bb[bs][row * PLD + c4]), Bg + (size_t)row * EMB + c * 32 + c4);
        }
        CP_COMMIT();
    };
    auto convert = [&](int bs) {                   // fp32 -> tf32 bits, in place
        #pragma unroll
        for (int i = 0; i < 4; i++) {              // 1024 slots; body does A and B
            int idx = tid + 256 * i;
            int row = idx >> 3, c4 = (idx & 7) * 4;
            float4* pa = (float4*)&Ab[bs][row * PLD + c4];
            float4 va = *pa;
            va.x = f2tf_f(va.x); va.y = f2tf_f(va.y);
            va.z = f2tf_f(va.z); va.w = f2tf_f(va.w);
            *pa = va;
            float4* pb = (float4*)&Bb[bs][row * PLD + c4];
            float4 vb = *pb;
            vb.x = f2tf_f(vb.x); vb.y = f2tf_f(vb.y);
            vb.z = f2tf_f(vb.z); vb.w = f2tf_f(vb.w);
            *pb = vb;
        }
    };

    stage(0, 0);
    for (int c = 0; c < 24; c++) {
        __syncthreads();                 // prev compute finished before overwrite
        if (c + 1 < 24) { stage(c + 1, (c + 1) & 1); CP_WAIT1(); }
        else           { CP_WAIT0(); }
        __syncthreads();                 // chunk c landed, visible
        convert(c & 1);
        __syncthreads();                 // converted bits visible

        const float* Af = Ab[c & 1];
        const float* Bf = Bb[c & 1];
        #pragma unroll
        for (int ks = 0; ks < 4; ks++) {
            const int k0s = 8 * ks;
            unsigned a[4][4];
            #pragma unroll
            for (int mt = 0; mt < 4; mt++) {
                int ra = (64 * wy + 16 * mt + g) * PLD + k0s;
                a[mt][0] = __float_as_uint(Af[ra + t]);
                a[mt][1] = __float_as_uint(Af[ra + 8 * PLD + t]);
                a[mt][2] = __float_as_uint(Af[ra + t + 4]);
                a[mt][3] = __float_as_uint(Af[ra + 8 * PLD + t + 4]);
            }
            #pragma unroll
            for (int nt = 0; nt < 4; nt++) {
                int rb = (32 * wx + 8 * nt + g) * PLD + k0s;
                unsigned b0 = __float_as_uint(Bf[rb + t]);
                unsigned b1 = __float_as_uint(Bf[rb + t + 4]);
                #pragma unroll
                for (int mt = 0; mt < 4; mt++)
                    mma_tf(acc[mt][nt], a[mt][0], a[mt][1], a[mt][2], a[mt][3], b0, b1);
            }
        }
    }
}

// ============================================================================
// Kernel A: fused QKV projection.  grid (32, 6, 3); split-head output.
// Stores tf32-prerounded (acc+bias) so flash needs no conversions at all.
// ============================================================================
__global__ __launch_bounds__(256, 2) void qkv_gemm(
    const float* __restrict__ q, const float* __restrict__ k, const float* __restrict__ v,
    const float* __restrict__ WQ, const float* __restrict__ WK, const float* __restrict__ WV,
    const float* __restrict__ bQ, const float* __restrict__ bK, const float* __restrict__ bV)
{
    extern __shared__ float sh[];
    const int m0 = blockIdx.x * 128, n0 = blockIdx.y * 128, sel = blockIdx.z;
    const float* X    = (sel == 0) ? q  : (sel == 1) ? k  : v;
    const float* W    = (sel == 0) ? WQ : (sel == 1) ? WK : WV;
    const float* bias = (sel == 0) ? bQ : (sel == 1) ? bK : bV;
    float* dst        = (sel == 0) ? g_Qh : (sel == 1) ? g_Kh : g_Vh;

    float acc[4][4][4] = {};
    proj_core(X + (size_t)m0 * EMB, W + (size_t)n0 * EMB, acc, sh);

    const int tid = threadIdx.x, lane = tid & 31, wid = tid >> 5;
    const int g = lane >> 2, t = lane & 3;
    const int wy = wid >> 2, wx = wid & 3;
    #pragma unroll
    for (int mt = 0; mt < 4; mt++) {
        #pragma unroll
        for (int nt = 0; nt < 4; nt++) {
            int n = n0 + 32 * wx + 8 * nt + 2 * t;
            int h = n >> 6, d0 = n & 63;
            float bb0 = bias[n], bb1 = bias[n + 1];
            int row = m0 + 64 * wy + 16 * mt + g;
            {
                int s = row >> 1, bI = row & 1;
                float2 st = make_float2(f2tf_f(acc[mt][nt][0] + bb0),
                                        f2tf_f(acc[mt][nt][1] + bb1));
                *(float2*)&dst[((size_t)(bI * NHEAD + h) * S_LEN + s) * HD + d0] = st;
            }
            {
                int r2 = row + 8;
                int s = r2 >> 1, bI = r2 & 1;
                float2 st = make_float2(f2tf_f(acc[mt][nt][2] + bb0),
                                        f2tf_f(acc[mt][nt][3] + bb1));
                *(float2*)&dst[((size_t)(bI * NHEAD + h) * S_LEN + s) * HD + d0] = st;
            }
        }
    }
}

// ============================================================================
// Kernel D: output projection (separate launch; 192 blocks, 2 CTA/SM).
// ============================================================================
__global__ __launch_bounds__(256, 2) void out_gemm(
    const float* __restrict__ W, const float* __restrict__ bias, float* __restrict__ out)
{
    extern __shared__ float sh[];
    const int m0 = blockIdx.x * 128, n0 = blockIdx.y * 128;

    float acc[4][4][4] = {};
    proj_core(g_ctx + (size_t)m0 * EMB, W + (size_t)n0 * EMB, acc, sh);

    const int tid = threadIdx.x, lane = tid & 31, wid = tid >> 5;
    const int g = lane >> 2, t = lane & 3;
    const int wy = wid >> 2, wx = wid & 3;
    #pragma unroll
    for (int mt = 0; mt < 4; mt++) {
        #pragma unroll
        for (int nt = 0; nt < 4; nt++) {
            int n = n0 + 32 * wx + 8 * nt + 2 * t;
            float bb0 = bias[n], bb1 = bias[n + 1];
            int row = m0 + 64 * wy + 16 * mt + g;
            *(float2*)&out[(size_t)row * EMB + n] =
                make_float2(acc[mt][nt][0] + bb0, acc[mt][nt][1] + bb1);
            *(float2*)&out[(size_t)(row + 8) * EMB + n] =
                make_float2(acc[mt][nt][2] + bb0, acc[mt][nt][3] + bb1);
        }
    }
}

// ============================================================================
// Kernel B: flash attention, tf32 mma.  grid (16, 24), 256 thr, 2 CTA/SM.
// Inputs arrive tf32-prerounded -> inner loops are pure LDS -> MMA.
// Warp w owns q-rows [16w,16w+16); raw scores streamed to wraw; m/l saved
// to g_m/g_l for the separate full-occupancy normalize kernel.
// Pads: Q/K/P = 68, V = 72 (conflict-free for their access patterns).
// ============================================================================
#define QPAD 68
#define KPAD 68
#define VPAD 72
#define PPAD 68
#define FLASH_SMEM ((128*QPAD + 64*KPAD + 64*VPAD + 128*PPAD) * 4)   // 105472 B

__global__ __launch_bounds__(256, 2) void flash_tc(float* __restrict__ wraw)
{
    extern __shared__ float sh[];
    float* Qs = sh;                          // [128][QPAD] tf32 bits
    float* Ks = Qs + 128 * QPAD;             // [64][KPAD]  tf32 bits
    float* Vs = Ks + 64 * KPAD;              // [64][VPAD]  tf32 bits
    float* Ps = Vs + 64 * VPAD;              // [128][PPAD] per-warp P tiles

    const int tid = threadIdx.x, lane = tid & 31, wid = tid >> 5;
    const int g = lane >> 2, t = lane & 3;
    const int hn = blockIdx.y;               // flattened head
    const int q0 = blockIdx.x * 128;

    const float* Qb = g_Qh + ((size_t)hn * S_LEN + q0) * HD;
    const float* Kb = g_Kh + (size_t)hn * S_LEN * HD;
    const float* Vb = g_Vh + (size_t)hn * S_LEN * HD;

    // preamble: stage Q, K0, V0 (already tf32 bits in gmem)
    #pragma unroll
    for (int i = 0; i < 8; i++) {
        int idx = tid + 256 * i; int row = idx >> 4, c4 = (idx & 15) * 4;
        cpa16(sm_addr(&Qs[row * QPAD + c4]), Qb + (size_t)row * HD + c4);
    }
    #pragma unroll
    for (int i = 0; i < 4; i++) {
        int idx = tid + 256 * i; int row = idx >> 4, c4 = (idx & 15) * 4;
        cpa16(sm_addr(&Ks[row * KPAD + c4]), Kb + (size_t)row * HD + c4);
        cpa16(sm_addr(&Vs[row * VPAD + c4]), Vb + (size_t)row * HD + c4);
    }
    CP_COMMIT();
    CP_WAIT0();

    float m0 = -INFINITY, m1 = -INFINITY, l0 = 0.f, l1 = 0.f;
    float oa[8][4] = {};
    const int qr = 16 * wid + g;             // warp-local base row (second = qr+8)
    float* Pw = Ps + wid * 16 * PPAD;        // per-warp P tile

    for (int kt = 0; kt < 32; kt++) {
        __syncthreads();                     // kt=0: preamble visible; kt>0: tail pair
        if (kt) { CP_WAIT0(); __syncthreads(); }   // K(kt), V(kt) landed + visible

        // ---- S = Q @ K^T / 8 ----
        float sa[8][4] = {};
        #pragma unroll
        for (int k8 = 0; k8 < 8; k8++) {
            int ra = qr * QPAD + 8 * k8;
            unsigned a0 = __float_as_uint(Qs[ra + t]);
            unsigned a1 = __float_as_uint(Qs[ra + 8 * QPAD + t]);
            unsigned a2 = __float_as_uint(Qs[ra + t + 4]);
            unsigned a3 = __float_as_uint(Qs[ra + 8 * QPAD + t + 4]);
            #pragma unroll
            for (int nt = 0; nt < 8; nt++) {
                int rb = (8 * nt + g) * KPAD + 8 * k8;
                mma_tf(sa[nt], a0, a1, a2, a3,
                       __float_as_uint(Ks[rb + t]),
                       __float_as_uint(Ks[rb + t + 4]));
            }
        }
        #pragma unroll
        for (int nt = 0; nt < 8; nt++) {
            sa[nt][0] *= 0.125f; sa[nt][1] *= 0.125f;
            sa[nt][2] *= 0.125f; sa[nt][3] *= 0.125f;
        }

        __syncthreads();                     // all warps done reading Ks
        if (kt < 31) {                       // prefetch K(kt+1) under softmax+PV
            #pragma unroll
            for (int i = 0; i < 4; i++) {
                int idx = tid + 256 * i; int row = idx >> 4, c4 = (idx & 15) * 4;
                cpa16(sm_addr(&Ks[row * KPAD + c4]),
                      Kb + (size_t)((kt + 1) * 64 + row) * HD + c4);
            }
            CP_COMMIT();
        }

        // ---- raw scores -> weights region (C layout: cols 2t,2t+1) ----
        if (wraw) {
            size_t rb0 = ((size_t)hn * S_LEN + (q0 + qr)) * S_LEN + (size_t)kt * 64 + 2 * t;
            #pragma unroll
            for (int nt = 0; nt < 8; nt++) {
                *(float2*)&wraw[rb0 + 8 * nt] = make_float2(sa[nt][0], sa[nt][1]);
                *(float2*)&wraw[rb0 + 8 * nt + 8 * (size_t)S_LEN] =
                    make_float2(sa[nt][2], sa[nt][3]);
            }
        }

        // ---- online softmax (row qr via c0/c1, row qr+8 via c2/c3) ----
        float lm0 = -INFINITY, lm1 = -INFINITY;
        #pragma unroll
        for (int nt = 0; nt < 8; nt++) {
            lm0 = fmaxf(lm0, fmaxf(sa[nt][0], sa[nt][1]));
            lm1 = fmaxf(lm1, fmaxf(sa[nt][2], sa[nt][3]));
        }
        lm0 = fmaxf(lm0, __shfl_xor_sync(0xffffffffu, lm0, 1));
        lm0 = fmaxf(lm0, __shfl_xor_sync(0xffffffffu, lm0, 2));
        lm1 = fmaxf(lm1, __shfl_xor_sync(0xffffffffu, lm1, 1));
        lm1 = fmaxf(lm1, __shfl_xor_sync(0xffffffffu, lm1, 2));
        float nm0 = fmaxf(m0, lm0), nm1 = fmaxf(m1, lm1);
        float ts0 = 0.f, ts1 = 0.f;
        #pragma unroll
        for (int nt = 0; nt < 8; nt++) {
            float p0 = __expf(sa[nt][0] - nm0);
            float p1 = __expf(sa[nt][1] - nm0);
            float p2 = __expf(sa[nt][2] - nm1);
            float p3 = __expf(sa[nt][3] - nm1);
            ts0 += p0 + p1; ts1 += p2 + p3;
            sa[nt][0] = f2tf_f(p0);          // tf32 bits, C layout
            sa[nt][1] = f2tf_f(p1);
            sa[nt][2] = f2tf_f(p2);
            sa[nt][3] = f2tf_f(p3);
        }
        ts0 += __shfl_xor_sync(0xffffffffu, ts0, 1);
        ts0 += __shfl_xor_sync(0xffffffffu, ts0, 2);
        ts1 += __shfl_xor_sync(0xffffffffu, ts1, 1);
        ts1 += __shfl_xor_sync(0xffffffffu, ts1, 2);
        float sc0 = __expf(m0 - nm0), sc1 = __expf(m1 - nm1);
        l0 = l0 * sc0 + ts0; l1 = l1 * sc1 + ts1;
        m0 = nm0; m1 = nm1;
        #pragma unroll
        for (int nt = 0; nt < 8; nt++) {
            oa[nt][0] *= sc0; oa[nt][1] *= sc0;
            oa[nt][2] *= sc1; oa[nt][3] *= sc1;
        }

        // ---- P: C-layout store to per-warp tile, A-layout reload ----
        #pragma unroll
        for (int nt = 0; nt < 8; nt++) {
            *(float2*)&Pw[g * PPAD + 8 * nt + 2 * t] =
                make_float2(sa[nt][0], sa[nt][1]);
            *(float2*)&Pw[(g + 8) * PPAD + 8 * nt + 2 * t] =
                make_float2(sa[nt][2], sa[nt][3]);
        }
        __syncwarp();

        // ---- O += P @ V ----
        #pragma unroll
        for (int k8 = 0; k8 < 8; k8++) {
            int pa = g * PPAD + 8 * k8;
            unsigned a0 = __float_as_uint(Pw[pa + t]);
            unsigned a1 = __float_as_uint(Pw[pa + 8 * PPAD + t]);
            unsigned a2 = __float_as_uint(Pw[pa + t + 4]);
            unsigned a3 = __float_as_uint(Pw[pa + t + 4 + 8 * PPAD]);
            #pragma unroll
            for (int nt = 0; nt < 8; nt++) {
                int vb = (8 * k8 + t) * VPAD + 8 * nt + g;
                mma_tf(oa[nt], a0, a1, a2, a3,
                       __float_as_uint(Vs[vb]),
                       __float_as_uint(Vs[vb + 4 * VPAD]));
            }
        }
        __syncthreads();                     // all warps done reading Vs
        if (kt < 31) {                       // prefetch V(kt+1)
            #pragma unroll
            for (int i = 0; i < 4; i++) {
                int idx = tid + 256 * i; int row = idx >> 4, c4 = (idx & 15) * 4;
                cpa16(sm_addr(&Vs[row * VPAD + c4]),
                      Vb + (size_t)((kt + 1) * 64 + row) * HD + c4);
            }
            CP_COMMIT();
        }
    }

    // epilogue: normalize, scatter ctx to [S,B,E], save (m,l) for norm kernel
    float inv0 = 1.f / l0, inv1 = 1.f / l1;
    const int r0 = q0 + qr, r1 = r0 + 8;
    const int bI = hn / NHEAD, hI = hn % NHEAD;
    #pragma unroll
    for (int nt = 0; nt < 8; nt++) {
        int d0 = 8 * nt + 2 * t;
        *(float2*)&g_ctx[((size_t)r0 * BATCH + bI) * EMB + hI * HD + d0] =
            make_float2(oa[nt][0] * inv0, oa[nt][1] * inv0);
        *(float2*)&g_ctx[((size_t)r1 * BATCH + bI) * EMB + hI * HD + d0] =
            make_float2(oa[nt][2] * inv1, oa[nt][3] * inv1);
    }
    if (t == 0) {
        g_m[hn * S_LEN + r0] = m0; g_m[hn * S_LEN + r1] = m1;
        g_l[hn * S_LEN + r0] = l0; g_l[hn * S_LEN + r1] = l1;
    }
}

// ============================================================================
// Kernel C: normalize raw scores in place: w = exp(s - m[row]) / l[row].
// Zero smem, full occupancy, one float4 per thread (measured 134us in R7).
// ============================================================================
__global__ __launch_bounds__(256) void softmax_norm_kernel(float* __restrict__ w)
{
    size_t i4 = (size_t)blockIdx.x * blockDim.x + threadIdx.x;
    size_t row = i4 / (S_LEN / 4);
    float m = g_m[row];
    float inv = 1.f / g_l[row];
    float4* wv = (float4*)w + i4;
    float4 v = *wv;
    v.x = __expf(v.x - m) * inv;
    v.y = __expf(v.y - m) * inv;
    v.z = __expf(v.z - m) * inv;
    v.w = __expf(v.w - m) * inv;
    *wv = v;
}

// ============================================================================
extern "C" void kernel_launch(void* const* d_in, const int* in_sizes, int n_in,
                              void* d_out, int out_size)
{
    const float* q   = (const float*)d_in[0];
    const float* k   = (const float*)d_in[1];
    const float* v   = (const float*)d_in[2];
    const float* W_Q = (const float*)d_in[3];
    const float* W_K = (const float*)d_in[4];
    const float* W_V = (const float*)d_in[5];
    const float* b_Q = (const float*)d_in[6];
    const float* b_K = (const float*)d_in[7];
    const float* b_V = (const float*)d_in[8];
    const float* W_O = (const float*)d_in[9];
    const float* b_O = (const float*)d_in[10];
    float* out = (float*)d_out;

    const long long NW_LL = (long long)NH * S_LEN * S_LEN;  // 100663296
    const long long total = (long long)OUT0 + NW_LL;
    float* wraw = ((long long)out_size >= total) ? (out + OUT0) : nullptr;

    cudaFuncSetAttribute(qkv_gemm,
                         cudaFuncAttributeMaxDynamicSharedMemorySize, PROJ_SMEM);
    cudaFuncSetAttribute(out_gemm,
                         cudaFuncAttributeMaxDynamicSharedMemorySize, PROJ_SMEM);
    cudaFuncSetAttribute(flash_tc,
                         cudaFuncAttributeMaxDynamicSharedMemorySize, FLASH_SMEM);

    dim3 gQKV(M_ROWS / 128, EMB / 128, 3);   // 32 x 6 x 3
    qkv_gemm<<<gQKV, 256, PROJ_SMEM>>>(q, k, v, W_Q, W_K, W_V, b_Q, b_K, b_V);

    dim3 gB(S_LEN / 128, NH);                // 16 x 24
    flash_tc<<<gB, 256, FLASH_SMEM>>>(wraw);

    if (wraw) {
        long long n4 = NW_LL / 4;            // 25165824 float4s
        int blocks = (int)(n4 / 256);        // 98304
        softmax_norm_kernel<<<blocks, 256>>>(wraw);
    }

    dim3 gO(M_ROWS / 128, EMB / 128);        // 32 x 6
    out_gemm<<<gO, 256, PROJ_SMEM>>>(W_O, b_O, out);
}

// round 13
// speedup vs baseline: 1.1882x; 1.0043x over previous
#include <cuda_runtime.h>
#include <math.h>

// Problem constants
#define S_LEN  2048
#define BATCH  2
#define EMB    768
#define NHEAD  12
#define HD     64
#define NH     (BATCH*NHEAD)        // 24 flattened heads
#define M_ROWS (S_LEN*BATCH)        // 4096
#define OUT0   (S_LEN*BATCH*EMB)    // 3145728 floats (output tensor)

// ---------------- device scratch (static, allocation-free) ----------------
// g_Qh/g_Kh/g_Vh hold tf32-PREROUNDED values (bit pattern of cvt.rna.tf32).
__device__ float g_Qh[NH * S_LEN * HD];   // [head, s, d]
__device__ float g_Kh[NH * S_LEN * HD];
__device__ float g_Vh[NH * S_LEN * HD];
__device__ float g_ctx[M_ROWS * EMB];     // attn_output in [S,B,E] layout (full fp32)
__device__ float g_m[NH * S_LEN];         // per-row softmax max
__device__ float g_l[NH * S_LEN];         // per-row softmax sum

// ============================================================================
// portable (compute_103-safe) helpers
// tf32 m16n8k8 fragment layouts (PTX ISA):
//  A (16x8):  a0=(g, t)  a1=(g+8, t)  a2=(g, t+4)  a3=(g+8, t+4)   [g=lane>>2, t=lane&3]
//  B (8x8):   b0=(k=t, n=g)  b1=(k=t+4, n=g)
//  C (16x8):  c0=(g, 2t) c1=(g, 2t+1) c2=(g+8, 2t) c3=(g+8, 2t+1)
// ============================================================================
__device__ __forceinline__ unsigned sm_addr(const void* p) {
    unsigned a;
    asm("{ .reg .u64 t; cvta.to.shared.u64 t, %1; cvt.u32.u64 %0, t; }" : "=r"(a) : "l"(p));
    return a;
}
__device__ __forceinline__ unsigned f2tf(float x) {
    unsigned r;
    asm("cvt.rna.tf32.f32 %0, %1;" : "=r"(r) : "f"(x));
    return r;
}
__device__ __forceinline__ float f2tf_f(float x) { return __uint_as_float(f2tf(x)); }

__device__ __forceinline__ void mma_tf(float c[4], unsigned a0, unsigned a1,
                                       unsigned a2, unsigned a3,
                                       unsigned b0, unsigned b1) {
    asm volatile(
        "mma.sync.aligned.m16n8k8.row.col.f32.tf32.tf32.f32 "
        "{%0,%1,%2,%3}, {%4,%5,%6,%7}, {%8,%9}, {%0,%1,%2,%3};"
        : "+f"(c[0]), "+f"(c[1]), "+f"(c[2]), "+f"(c[3])
        : "r"(a0), "r"(a1), "r"(a2), "r"(a3), "r"(b0), "r"(b1));
}
__device__ __forceinline__ void cpa16(unsigned saddr, const void* gptr) {
    asm volatile("cp.async.cg.shared.global [%0], [%1], 16;" :: "r"(saddr), "l"(gptr));
}
#define CP_COMMIT()  asm volatile("cp.async.commit_group;")
#define CP_WAIT0()   asm volatile("cp.async.wait_group 0;")
#define CP_WAIT1()   asm volatile("cp.async.wait_group 1;")

// ============================================================================
// Projection GEMM core: C[128x128] = A[128x768] @ B[128x768]^T (both K-major).
// 8 warps (2x4): warp tile 64m x 32n; K-chunks of 32, cp.async double-buffered.
// Each landed chunk is converted to tf32 bits IN SMEM (one vector pass), so the
// mma operand chains are pure LDS -> MMA (no F2FP in the critical path).
// ============================================================================
#define PLD 36
#define PROJ_SMEM (4 * 128 * PLD * 4)   // 73728 B

__device__ __forceinline__ void proj_core(const float* __restrict__ Ag,
                                          const float* __restrict__ Bg,
                                          float (&acc)[4][4][4], float* sh)
{
    float* Ab[2] = { sh,                 sh + 128 * PLD };
    float* Bb[2] = { sh + 2 * 128 * PLD, sh + 3 * 128 * PLD };
    const int tid = threadIdx.x;
    const int lane = tid & 31, wid = tid >> 5;
    const int g = lane >> 2, t = lane & 3;
    const int wy = wid >> 2, wx = wid & 3;

    auto stage = [&](int c, int bs) {
        #pragma unroll
        for (int i = 0; i < 4; i++) {
            int idx = tid + 256 * i;               // 0..1023 (float4 slots per tile)
            int row = idx >> 3, c4 = (idx & 7) * 4;
            cpa16(sm_addr(&Ab[bs][row * PLD + c4]), Ag + (size_t)row * EMB + c * 32 + c4);
            cpa16(sm_addr(&Bb[bs][row * PLD + c4]), Bg + (size_t)row * EMB + c * 32 + c4);
        }
        CP_COMMIT();
    };
    auto convert = [&](int bs) {                   // fp32 -> tf32 bits, in place
        #pragma unroll
        for (int i = 0; i < 4; i++) {              // 1024 slots; body does A and B
            int idx = tid + 256 * i;
            int row = idx >> 3, c4 = (idx & 7) * 4;
            float4* pa = (float4*)&Ab[bs][row * PLD + c4];
            float4 va = *pa;
            va.x = f2tf_f(va.x); va.y = f2tf_f(va.y);
            va.z = f2tf_f(va.z); va.w = f2tf_f(va.w);
            *pa = va;
            float4* pb = (float4*)&Bb[bs][row * PLD + c4];
            float4 vb = *pb;
            vb.x = f2tf_f(vb.x); vb.y = f2tf_f(vb.y);
            vb.z = f2tf_f(vb.z); vb.w = f2tf_f(vb.w);
            *pb = vb;
        }
    };

    stage(0, 0);
    for (int c = 0; c < 24; c++) {
        __syncthreads();                 // prev compute finished before overwrite
        if (c + 1 < 24) { stage(c + 1, (c + 1) & 1); CP_WAIT1(); }
        else           { CP_WAIT0(); }
        __syncthreads();                 // chunk c landed, visible
        convert(c & 1);
        __syncthreads();                 // converted bits visible

        const float* Af = Ab[c & 1];
        const float* Bf = Bb[c & 1];
        #pragma unroll
        for (int ks = 0; ks < 4; ks++) {
            const int k0s = 8 * ks;
            unsigned a[4][4];
            #pragma unroll
            for (int mt = 0; mt < 4; mt++) {
                int ra = (64 * wy + 16 * mt + g) * PLD + k0s;
                a[mt][0] = __float_as_uint(Af[ra + t]);
                a[mt][1] = __float_as_uint(Af[ra + 8 * PLD + t]);
                a[mt][2] = __float_as_uint(Af[ra + t + 4]);
                a[mt][3] = __float_as_uint(Af[ra + 8 * PLD + t + 4]);
            }
            #pragma unroll
            for (int nt = 0; nt < 4; nt++) {
                int rb = (32 * wx + 8 * nt + g) * PLD + k0s;
                unsigned b0 = __float_as_uint(Bf[rb + t]);
                unsigned b1 = __float_as_uint(Bf[rb + t + 4]);
                #pragma unroll
                for (int mt = 0; mt < 4; mt++)
                    mma_tf(acc[mt][nt], a[mt][0], a[mt][1], a[mt][2], a[mt][3], b0, b1);
            }
        }
    }
}

// ============================================================================
// Kernel A: fused QKV projection.  grid (32, 6, 3); split-head output.
// Stores tf32-prerounded (acc+bias) so flash needs no conversions at all.
// ============================================================================
__global__ __launch_bounds__(256, 2) void qkv_gemm(
    const float* __restrict__ q, const float* __restrict__ k, const float* __restrict__ v,
    const float* __restrict__ WQ, const float* __restrict__ WK, const float* __restrict__ WV,
    const float* __restrict__ bQ, const float* __restrict__ bK, const float* __restrict__ bV)
{
    extern __shared__ float sh[];
    const int m0 = blockIdx.x * 128, n0 = blockIdx.y * 128, sel = blockIdx.z;
    const float* X    = (sel == 0) ? q  : (sel == 1) ? k  : v;
    const float* W    = (sel == 0) ? WQ : (sel == 1) ? WK : WV;
    const float* bias = (sel == 0) ? bQ : (sel == 1) ? bK : bV;
    float* dst        = (sel == 0) ? g_Qh : (sel == 1) ? g_Kh : g_Vh;

    float acc[4][4][4] = {};
    proj_core(X + (size_t)m0 * EMB, W + (size_t)n0 * EMB, acc, sh);

    const int tid = threadIdx.x, lane = tid & 31, wid = tid >> 5;
    const int g = lane >> 2, t = lane & 3;
    const int wy = wid >> 2, wx = wid & 3;
    #pragma unroll
    for (int mt = 0; mt < 4; mt++) {
        #pragma unroll
        for (int nt = 0; nt < 4; nt++) {
            int n = n0 + 32 * wx + 8 * nt + 2 * t;
            int h = n >> 6, d0 = n & 63;
            float bb0 = bias[n], bb1 = bias[n + 1];
            int row = m0 + 64 * wy + 16 * mt + g;
            {
                int s = row >> 1, bI = row & 1;
                float2 st = make_float2(f2tf_f(acc[mt][nt][0] + bb0),
                                        f2tf_f(acc[mt][nt][1] + bb1));
                *(float2*)&dst[((size_t)(bI * NHEAD + h) * S_LEN + s) * HD + d0] = st;
            }
            {
                int r2 = row + 8;
                int s = r2 >> 1, bI = r2 & 1;
                float2 st = make_float2(f2tf_f(acc[mt][nt][2] + bb0),
                                        f2tf_f(acc[mt][nt][3] + bb1));
                *(float2*)&dst[((size_t)(bI * NHEAD + h) * S_LEN + s) * HD + d0] = st;
            }
        }
    }
}

// ============================================================================
// Kernel D: output projection (192 blocks, 2 CTA/SM; runs CONCURRENT with norm)
// ============================================================================
__global__ __launch_bounds__(256, 2) void out_gemm(
    const float* __restrict__ W, const float* __restrict__ bias, float* __restrict__ out)
{
    extern __shared__ float sh[];
    const int m0 = blockIdx.x * 128, n0 = blockIdx.y * 128;

    float acc[4][4][4] = {};
    proj_core(g_ctx + (size_t)m0 * EMB, W + (size_t)n0 * EMB, acc, sh);

    const int tid = threadIdx.x, lane = tid & 31, wid = tid >> 5;
    const int g = lane >> 2, t = lane & 3;
    const int wy = wid >> 2, wx = wid & 3;
    #pragma unroll
    for (int mt = 0; mt < 4; mt++) {
        #pragma unroll
        for (int nt = 0; nt < 4; nt++) {
            int n = n0 + 32 * wx + 8 * nt + 2 * t;
            float bb0 = bias[n], bb1 = bias[n + 1];
            int row = m0 + 64 * wy + 16 * mt + g;
            *(float2*)&out[(size_t)row * EMB + n] =
                make_float2(acc[mt][nt][0] + bb0, acc[mt][nt][1] + bb1);
            *(float2*)&out[(size_t)(row + 8) * EMB + n] =
                make_float2(acc[mt][nt][2] + bb0, acc[mt][nt][3] + bb1);
        }
    }
}

// ============================================================================
// Kernel B: flash attention, tf32 mma.  grid (16, 24), 256 thr, 2 CTA/SM.
// Inputs arrive tf32-prerounded -> inner loops are pure LDS -> MMA.
// Warp w owns q-rows [16w,16w+16); raw scores streamed to wraw; m/l saved
// to g_m/g_l for the separate full-occupancy normalize kernel.
// Pads: Q/K/P = 68, V = 72 (conflict-free for their access patterns).
// ============================================================================
#define QPAD 68
#define KPAD 68
#define VPAD 72
#define PPAD 68
#define FLASH_SMEM ((128*QPAD + 64*KPAD + 64*VPAD + 128*PPAD) * 4)   // 105472 B

__global__ __launch_bounds__(256, 2) void flash_tc(float* __restrict__ wraw)
{
    extern __shared__ float sh[];
    float* Qs = sh;                          // [128][QPAD] tf32 bits
    float* Ks = Qs + 128 * QPAD;             // [64][KPAD]  tf32 bits
    float* Vs = Ks + 64 * KPAD;              // [64][VPAD]  tf32 bits
    float* Ps = Vs + 64 * VPAD;              // [128][PPAD] per-warp P tiles

    const int tid = threadIdx.x, lane = tid & 31, wid = tid >> 5;
    const int g = lane >> 2, t = lane & 3;
    const int hn = blockIdx.y;               // flattened head
    const int q0 = blockIdx.x * 128;

    const float* Qb = g_Qh + ((size_t)hn * S_LEN + q0) * HD;
    const float* Kb = g_Kh + (size_t)hn * S_LEN * HD;
    const float* Vb = g_Vh + (size_t)hn * S_LEN * HD;

    // preamble: stage Q, K0, V0 (already tf32 bits in gmem)
    #pragma unroll
    for (int i = 0; i < 8; i++) {
        int idx = tid + 256 * i; int row = idx >> 4, c4 = (idx & 15) * 4;
        cpa16(sm_addr(&Qs[row * QPAD + c4]), Qb + (size_t)row * HD + c4);
    }
    #pragma unroll
    for (int i = 0; i < 4; i++) {
        int idx = tid + 256 * i; int row = idx >> 4, c4 = (idx & 15) * 4;
        cpa16(sm_addr(&Ks[row * KPAD + c4]), Kb + (size_t)row * HD + c4);
        cpa16(sm_addr(&Vs[row * VPAD + c4]), Vb + (size_t)row * HD + c4);
    }
    CP_COMMIT();
    CP_WAIT0();

    float m0 = -INFINITY, m1 = -INFINITY, l0 = 0.f, l1 = 0.f;
    float oa[8][4] = {};
    const int qr = 16 * wid + g;             // warp-local base row (second = qr+8)
    float* Pw = Ps + wid * 16 * PPAD;        // per-warp P tile

    for (int kt = 0; kt < 32; kt++) {
        __syncthreads();                     // kt=0: preamble visible; kt>0: tail pair
        if (kt) { CP_WAIT0(); __syncthreads(); }   // K(kt), V(kt) landed + visible

        // ---- S = Q @ K^T / 8 ----
        float sa[8][4] = {};
        #pragma unroll
        for (int k8 = 0; k8 < 8; k8++) {
            int ra = qr * QPAD + 8 * k8;
            unsigned a0 = __float_as_uint(Qs[ra + t]);
            unsigned a1 = __float_as_uint(Qs[ra + 8 * QPAD + t]);
            unsigned a2 = __float_as_uint(Qs[ra + t + 4]);
            unsigned a3 = __float_as_uint(Qs[ra + 8 * QPAD + t + 4]);
            #pragma unroll
            for (int nt = 0; nt < 8; nt++) {
                int rb = (8 * nt + g) * KPAD + 8 * k8;
                mma_tf(sa[nt], a0, a1, a2, a3,
                       __float_as_uint(Ks[rb + t]),
                       __float_as_uint(Ks[rb + t + 4]));
            }
        }
        #pragma unroll
        for (int nt = 0; nt < 8; nt++) {
            sa[nt][0] *= 0.125f; sa[nt][1] *= 0.125f;
            sa[nt][2] *= 0.125f; sa[nt][3] *= 0.125f;
        }

        __syncthreads();                     // all warps done reading Ks
        if (kt < 31) {                       // prefetch K(kt+1) under softmax+PV
            #pragma unroll
            for (int i = 0; i < 4; i++) {
                int idx = tid + 256 * i; int row = idx >> 4, c4 = (idx & 15) * 4;
                cpa16(sm_addr(&Ks[row * KPAD + c4]),
                      Kb + (size_t)((kt + 1) * 64 + row) * HD + c4);
            }
            CP_COMMIT();
        }

        // ---- raw scores -> weights region (C layout: cols 2t,2t+1) ----
        if (wraw) {
            size_t rb0 = ((size_t)hn * S_LEN + (q0 + qr)) * S_LEN + (size_t)kt * 64 + 2 * t;
            #pragma unroll
            for (int nt = 0; nt < 8; nt++) {
                *(float2*)&wraw[rb0 + 8 * nt] = make_float2(sa[nt][0], sa[nt][1]);
                *(float2*)&wraw[rb0 + 8 * nt + 8 * (size_t)S_LEN] =
                    make_float2(sa[nt][2], sa[nt][3]);
            }
        }

        // ---- online softmax (row qr via c0/c1, row qr+8 via c2/c3) ----
        float lm0 = -INFINITY, lm1 = -INFINITY;
        #pragma unroll
        for (int nt = 0; nt < 8; nt++) {
            lm0 = fmaxf(lm0, fmaxf(sa[nt][0], sa[nt][1]));
            lm1 = fmaxf(lm1, fmaxf(sa[nt][2], sa[nt][3]));
        }
        lm0 = fmaxf(lm0, __shfl_xor_sync(0xffffffffu, lm0, 1));
        lm0 = fmaxf(lm0, __shfl_xor_sync(0xffffffffu, lm0, 2));
        lm1 = fmaxf(lm1, __shfl_xor_sync(0xffffffffu, lm1, 1));
        lm1 = fmaxf(lm1, __shfl_xor_sync(0xffffffffu, lm1, 2));
        float nm0 = fmaxf(m0, lm0), nm1 = fmaxf(m1, lm1);
        float ts0 = 0.f, ts1 = 0.f;
        #pragma unroll
        for (int nt = 0; nt < 8; nt++) {
            float p0 = __expf(sa[nt][0] - nm0);
            float p1 = __expf(sa[nt][1] - nm0);
            float p2 = __expf(sa[nt][2] - nm1);
            float p3 = __expf(sa[nt][3] - nm1);
            ts0 += p0 + p1; ts1 += p2 + p3;
            sa[nt][0] = f2tf_f(p0);          // tf32 bits, C layout
            sa[nt][1] = f2tf_f(p1);
            sa[nt][2] = f2tf_f(p2);
            sa[nt][3] = f2tf_f(p3);
        }
        ts0 += __shfl_xor_sync(0xffffffffu, ts0, 1);
        ts0 += __shfl_xor_sync(0xffffffffu, ts0, 2);
        ts1 += __shfl_xor_sync(0xffffffffu, ts1, 1);
        ts1 += __shfl_xor_sync(0xffffffffu, ts1, 2);
        float sc0 = __expf(m0 - nm0), sc1 = __expf(m1 - nm1);
        l0 = l0 * sc0 + ts0; l1 = l1 * sc1 + ts1;
        m0 = nm0; m1 = nm1;
        #pragma unroll
        for (int nt = 0; nt < 8; nt++) {
            oa[nt][0] *= sc0; oa[nt][1] *= sc0;
            oa[nt][2] *= sc1; oa[nt][3] *= sc1;
        }

        // ---- P: C-layout store to per-warp tile, A-layout reload ----
        #pragma unroll
        for (int nt = 0; nt < 8; nt++) {
            *(float2*)&Pw[g * PPAD + 8 * nt + 2 * t] =
                make_float2(sa[nt][0], sa[nt][1]);
            *(float2*)&Pw[(g + 8) * PPAD + 8 * nt + 2 * t] =
                make_float2(sa[nt][2], sa[nt][3]);
        }
        __syncwarp();

        // ---- O += P @ V ----
        #pragma unroll
        for (int k8 = 0; k8 < 8; k8++) {
            int pa = g * PPAD + 8 * k8;
            unsigned a0 = __float_as_uint(Pw[pa + t]);
            unsigned a1 = __float_as_uint(Pw[pa + 8 * PPAD + t]);
            unsigned a2 = __float_as_uint(Pw[pa + t + 4]);
            unsigned a3 = __float_as_uint(Pw[pa + t + 4 + 8 * PPAD]);
            #pragma unroll
            for (int nt = 0; nt < 8; nt++) {
                int vb = (8 * k8 + t) * VPAD + 8 * nt + g;
                mma_tf(oa[nt], a0, a1, a2, a3,
                       __float_as_uint(Vs[vb]),
                       __float_as_uint(Vs[vb + 4 * VPAD]));
            }
        }
        __syncthreads();                     // all warps done reading Vs
        if (kt < 31) {                       // prefetch V(kt+1)
            #pragma unroll
            for (int i = 0; i < 4; i++) {
                int idx = tid + 256 * i; int row = idx >> 4, c4 = (idx & 15) * 4;
                cpa16(sm_addr(&Vs[row * VPAD + c4]),
                      Vb + (size_t)((kt + 1) * 64 + row) * HD + c4);
            }
            CP_COMMIT();
        }
    }

    // epilogue: normalize, scatter ctx to [S,B,E], save (m,l) for norm kernel
    float inv0 = 1.f / l0, inv1 = 1.f / l1;
    const int r0 = q0 + qr, r1 = r0 + 8;
    const int bI = hn / NHEAD, hI = hn % NHEAD;
    #pragma unroll
    for (int nt = 0; nt < 8; nt++) {
        int d0 = 8 * nt + 2 * t;
        *(float2*)&g_ctx[((size_t)r0 * BATCH + bI) * EMB + hI * HD + d0] =
            make_float2(oa[nt][0] * inv0, oa[nt][1] * inv0);
        *(float2*)&g_ctx[((size_t)r1 * BATCH + bI) * EMB + hI * HD + d0] =
            make_float2(oa[nt][2] * inv1, oa[nt][3] * inv1);
    }
    if (t == 0) {
        g_m[hn * S_LEN + r0] = m0; g_m[hn * S_LEN + r1] = m1;
        g_l[hn * S_LEN + r0] = l0; g_l[hn * S_LEN + r1] = l1;
    }
}

// ============================================================================
// Kernel C: normalize raw scores in place: w = exp(s - m[row]) / l[row].
// Zero smem, full occupancy, one float4 per thread.
// ============================================================================
__global__ __launch_bounds__(256) void softmax_norm_kernel(float* __restrict__ w)
{
    size_t i4 = (size_t)blockIdx.x * blockDim.x + threadIdx.x;
    size_t row = i4 / (S_LEN / 4);
    float m = g_m[row];
    float inv = 1.f / g_l[row];
    float4* wv = (float4*)w + i4;
    float4 v = *wv;
    v.x = __expf(v.x - m) * inv;
    v.y = __expf(v.y - m) * inv;
    v.z = __expf(v.z - m) * inv;
    v.w = __expf(v.w - m) * inv;
    *wv = v;
}

// ============================================================================
extern "C" void kernel_launch(void* const* d_in, const int* in_sizes, int n_in,
                              void* d_out, int out_size)
{
    const float* q   = (const float*)d_in[0];
    const float* k   = (const float*)d_in[1];
    const float* v   = (const float*)d_in[2];
    const float* W_Q = (const float*)d_in[3];
    const float* W_K = (const float*)d_in[4];
    const float* W_V = (const float*)d_in[5];
    const float* b_Q = (const float*)d_in[6];
    const float* b_K = (const float*)d_in[7];
    const float* b_V = (const float*)d_in[8];
    const float* W_O = (const float*)d_in[9];
    const float* b_O = (const float*)d_in[10];
    float* out = (float*)d_out;

    const long long NW_LL = (long long)NH * S_LEN * S_LEN;  // 100663296
    const long long total = (long long)OUT0 + NW_LL;
    float* wraw = ((long long)out_size >= total) ? (out + OUT0) : nullptr;

    cudaFuncSetAttribute(qkv_gemm,
                         cudaFuncAttributeMaxDynamicSharedMemorySize, PROJ_SMEM);
    cudaFuncSetAttribute(out_gemm,
                         cudaFuncAttributeMaxDynamicSharedMemorySize, PROJ_SMEM);
    cudaFuncSetAttribute(flash_tc,
                         cudaFuncAttributeMaxDynamicSharedMemorySize, FLASH_SMEM);

    // Lazily-created side stream + events for the norm ∥ out_gemm graph fork.
    // Created once, never destroyed (destroying mid-capture would invalidate
    // the capture). Creation is host-side resource setup, not device memory.
    static cudaStream_t s_norm = nullptr;
    static cudaEvent_t ev_fork = nullptr, ev_join = nullptr;
    if (!s_norm) {
        cudaStreamCreateWithFlags(&s_norm, cudaStreamNonBlocking);
        cudaEventCreateWithFlags(&ev_fork, cudaEventDisableTiming);
        cudaEventCreateWithFlags(&ev_join, cudaEventDisableTiming);
    }

    dim3 gQKV(M_ROWS / 128, EMB / 128, 3);   // 32 x 6 x 3
    qkv_gemm<<<gQKV, 256, PROJ_SMEM>>>(q, k, v, W_Q, W_K, W_V, b_Q, b_K, b_V);

    dim3 gB(S_LEN / 128, NH);                // 16 x 24
    flash_tc<<<gB, 256, FLASH_SMEM>>>(wraw);

    // Fork: softmax-normalize (HBM-bound) runs concurrently with the
    // out-projection GEMM (latency/tensor-bound, only 96 of 148 SMs busy).
    // Both depend only on flash_tc; join before returning.
    bool forked = false;
    if (wraw) {
        cudaEventRecord(ev_fork, 0);
        if (cudaStreamWaitEvent(s_norm, ev_fork, 0) == cudaSuccess) {
            long long n4 = NW_LL / 4;            // 25165824 float4s
            int blocks = (int)(n4 / 256);        // 98304
            softmax_norm_kernel<<<blocks, 256, 0, s_norm>>>(wraw);
            cudaEventRecord(ev_join, s_norm);
            forked = true;
        } else {
            // fallback: serial norm on the main stream
            long long n4 = NW_LL / 4;
            int blocks = (int)(n4 / 256);
            softmax_norm_kernel<<<blocks, 256>>>(wraw);
        }
    }

    dim3 gO(M_ROWS / 128, EMB / 128);        // 32 x 6
    out_gemm<<<gO, 256, PROJ_SMEM>>>(W_O, b_O, out);

    if (forked) cudaStreamWaitEvent(0, ev_join, 0);
}

// round 14
// speedup vs baseline: 1.1974x; 1.0077x over previous
#include <cuda_runtime.h>
#include <math.h>

// Problem constants
#define S_LEN  2048
#define BATCH  2
#define EMB    768
#define NHEAD  12
#define HD     64
#define NH     (BATCH*NHEAD)        // 24 flattened heads
#define M_ROWS (S_LEN*BATCH)        // 4096
#define OUT0   (S_LEN*BATCH*EMB)    // 3145728 floats (output tensor)

// ---------------- device scratch (static, allocation-free) ----------------
// g_Qh/g_Kh/g_Vh hold tf32-PREROUNDED values (bit pattern of cvt.rna.tf32).
__device__ float g_Qh[NH * S_LEN * HD];   // [head, s, d]
__device__ float g_Kh[NH * S_LEN * HD];
__device__ float g_Vh[NH * S_LEN * HD];
__device__ float g_ctx[M_ROWS * EMB];     // attn_output in [S,B,E] layout (full fp32)
__device__ float g_m[NH * S_LEN];         // per-row softmax max
__device__ float g_l[NH * S_LEN];         // per-row softmax sum

// ============================================================================
// portable (compute_103-safe) helpers
// tf32 m16n8k8 fragment layouts (PTX ISA):
//  A (16x8):  a0=(g, t)  a1=(g+8, t)  a2=(g, t+4)  a3=(g+8, t+4)   [g=lane>>2, t=lane&3]
//  B (8x8):   b0=(k=t, n=g)  b1=(k=t+4, n=g)
//  C (16x8):  c0=(g, 2t) c1=(g, 2t+1) c2=(g+8, 2t) c3=(g+8, 2t+1)
// ============================================================================
__device__ __forceinline__ unsigned sm_addr(const void* p) {
    unsigned a;
    asm("{ .reg .u64 t; cvta.to.shared.u64 t, %1; cvt.u32.u64 %0, t; }" : "=r"(a) : "l"(p));
    return a;
}
__device__ __forceinline__ unsigned f2tf(float x) {
    unsigned r;
    asm("cvt.rna.tf32.f32 %0, %1;" : "=r"(r) : "f"(x));
    return r;
}
__device__ __forceinline__ float f2tf_f(float x) { return __uint_as_float(f2tf(x)); }

__device__ __forceinline__ void mma_tf(float c[4], unsigned a0, unsigned a1,
                                       unsigned a2, unsigned a3,
                                       unsigned b0, unsigned b1) {
    asm volatile(
        "mma.sync.aligned.m16n8k8.row.col.f32.tf32.tf32.f32 "
        "{%0,%1,%2,%3}, {%4,%5,%6,%7}, {%8,%9}, {%0,%1,%2,%3};"
        : "+f"(c[0]), "+f"(c[1]), "+f"(c[2]), "+f"(c[3])
        : "r"(a0), "r"(a1), "r"(a2), "r"(a3), "r"(b0), "r"(b1));
}
__device__ __forceinline__ void cpa16(unsigned saddr, const void* gptr) {
    asm volatile("cp.async.cg.shared.global [%0], [%1], 16;" :: "r"(saddr), "l"(gptr));
}
#define CP_COMMIT()  asm volatile("cp.async.commit_group;")
#define CP_WAIT0()   asm volatile("cp.async.wait_group 0;")
#define CP_WAIT1()   asm volatile("cp.async.wait_group 1;")

// ============================================================================
// Projection GEMM core: C[128x128] = A[128x768] @ B[128x768]^T (both K-major).
// 8 warps (2x4): warp tile 64m x 32n; K-chunks of 32.
// THREE-stage cp.async pipeline (prefetch distance 2): each chunk's loads get
// ~2 compute iterations to land, hiding the ~600-1000cyc DRAM/L2 latency that
// previously exposed a bubble every chunk (issue% was 22-28).
// Each landed chunk is converted to tf32 bits IN SMEM (one vector pass).
// ============================================================================
#define PLD 36
#define PBUF (128 * PLD)                 // floats per tile
#define PROJ_SMEM (6 * PBUF * 4)         // 110592 B (3 x A + 3 x B)

__device__ __forceinline__ void proj_core(const float* __restrict__ Ag,
                                          const float* __restrict__ Bg,
                                          float (&acc)[4][4][4], float* sh)
{
    float* Ab[3] = { sh,            sh + PBUF,     sh + 2 * PBUF };
    float* Bb[3] = { sh + 3 * PBUF, sh + 4 * PBUF, sh + 5 * PBUF };
    const int tid = threadIdx.x;
    const int lane = tid & 31, wid = tid >> 5;
    const int g = lane >> 2, t = lane & 3;
    const int wy = wid >> 2, wx = wid & 3;

    auto stage = [&](int c, int bs) {
        #pragma unroll
        for (int i = 0; i < 4; i++) {
            int idx = tid + 256 * i;               // 0..1023 (float4 slots per tile)
            int row = idx >> 3, c4 = (idx & 7) * 4;
            cpa16(sm_addr(&Ab[bs][row * PLD + c4]), Ag + (size_t)row * EMB + c * 32 + c4);
            cpa16(sm_addr(&Bb[bs][row * PLD + c4]), Bg + (size_t)row * EMB + c * 32 + c4);
        }
        CP_COMMIT();
    };
    auto convert = [&](int bs) {                   // fp32 -> tf32 bits, in place
        #pragma unroll
        for (int i = 0; i < 4; i++) {              // 1024 slots; body does A and B
            int idx = tid + 256 * i;
            int row = idx >> 3, c4 = (idx & 7) * 4;
            float4* pa = (float4*)&Ab[bs][row * PLD + c4];
            float4 va = *pa;
            va.x = f2tf_f(va.x); va.y = f2tf_f(va.y);
            va.z = f2tf_f(va.z); va.w = f2tf_f(va.w);
            *pa = va;
            float4* pb = (float4*)&Bb[bs][row * PLD + c4];
            float4 vb = *pb;
            vb.x = f2tf_f(vb.x); vb.y = f2tf_f(vb.y);
            vb.z = f2tf_f(vb.z); vb.w = f2tf_f(vb.w);
            *pb = vb;
        }
    };

    stage(0, 0);
    stage(1, 1);
    for (int c = 0; c < 24; c++) {
        // chunk c landed?  groups committed after c: {c+1, c+2} while c<22.
        if (c < 23) { CP_WAIT1(); } else { CP_WAIT0(); }
        __syncthreads();                 // (a) all warps done computing chunk c-1
                                         // (b) chunk c's landed bytes visible
        convert(c % 3);
        __syncthreads();                 // converted bits visible

        const float* Af = Ab[c % 3];
        const float* Bf = Bb[c % 3];
        #pragma unroll
        for (int ks = 0; ks < 4; ks++) {
            const int k0s = 8 * ks;
            unsigned a[4][4];
            #pragma unroll
            for (int mt = 0; mt < 4; mt++) {
                int ra = (64 * wy + 16 * mt + g) * PLD + k0s;
                a[mt][0] = __float_as_uint(Af[ra + t]);
                a[mt][1] = __float_as_uint(Af[ra + 8 * PLD + t]);
                a[mt][2] = __float_as_uint(Af[ra + t + 4]);
                a[mt][3] = __float_as_uint(Af[ra + 8 * PLD + t + 4]);
            }
            #pragma unroll
            for (int nt = 0; nt < 4; nt++) {
                int rb = (32 * wx + 8 * nt + g) * PLD + k0s;
                unsigned b0 = __float_as_uint(Bf[rb + t]);
                unsigned b1 = __float_as_uint(Bf[rb + t + 4]);
                #pragma unroll
                for (int mt = 0; mt < 4; mt++)
                    mma_tf(acc[mt][nt], a[mt][0], a[mt][1], a[mt][2], a[mt][3], b0, b1);
            }
        }

        // stage chunk c+2 into buffer (c+2)%3 == (c-1)%3, freed by barrier (a)
        if (c + 2 < 24) stage(c + 2, (c + 2) % 3);
    }
}

// ============================================================================
// Kernel A: fused QKV projection.  grid (32, 6, 3); split-head output.
// Stores tf32-prerounded (acc+bias) so flash needs no conversions at all.
// ============================================================================
__global__ __launch_bounds__(256, 2) void qkv_gemm(
    const float* __restrict__ q, const float* __restrict__ k, const float* __restrict__ v,
    const float* __restrict__ WQ, const float* __restrict__ WK, const float* __restrict__ WV,
    const float* __restrict__ bQ, const float* __restrict__ bK, const float* __restrict__ bV)
{
    extern __shared__ float sh[];
    const int m0 = blockIdx.x * 128, n0 = blockIdx.y * 128, sel = blockIdx.z;
    const float* X    = (sel == 0) ? q  : (sel == 1) ? k  : v;
    const float* W    = (sel == 0) ? WQ : (sel == 1) ? WK : WV;
    const float* bias = (sel == 0) ? bQ : (sel == 1) ? bK : bV;
    float* dst        = (sel == 0) ? g_Qh : (sel == 1) ? g_Kh : g_Vh;

    float acc[4][4][4] = {};
    proj_core(X + (size_t)m0 * EMB, W + (size_t)n0 * EMB, acc, sh);

    const int tid = threadIdx.x, lane = tid & 31, wid = tid >> 5;
    const int g = lane >> 2, t = lane & 3;
    const int wy = wid >> 2, wx = wid & 3;
    #pragma unroll
    for (int mt = 0; mt < 4; mt++) {
        #pragma unroll
        for (int nt = 0; nt < 4; nt++) {
            int n = n0 + 32 * wx + 8 * nt + 2 * t;
            int h = n >> 6, d0 = n & 63;
            float bb0 = bias[n], bb1 = bias[n + 1];
            int row = m0 + 64 * wy + 16 * mt + g;
            {
                int s = row >> 1, bI = row & 1;
                float2 st = make_float2(f2tf_f(acc[mt][nt][0] + bb0),
                                        f2tf_f(acc[mt][nt][1] + bb1));
                *(float2*)&dst[((size_t)(bI * NHEAD + h) * S_LEN + s) * HD + d0] = st;
            }
            {
                int r2 = row + 8;
                int s = r2 >> 1, bI = r2 & 1;
                float2 st = make_float2(f2tf_f(acc[mt][nt][2] + bb0),
                                        f2tf_f(acc[mt][nt][3] + bb1));
                *(float2*)&dst[((size_t)(bI * NHEAD + h) * S_LEN + s) * HD + d0] = st;
            }
        }
    }
}

// ============================================================================
// Kernel D: output projection (192 blocks, 2 CTA/SM).
// ============================================================================
__global__ __launch_bounds__(256, 2) void out_gemm(
    const float* __restrict__ W, const float* __restrict__ bias, float* __restrict__ out)
{
    extern __shared__ float sh[];
    const int m0 = blockIdx.x * 128, n0 = blockIdx.y * 128;

    float acc[4][4][4] = {};
    proj_core(g_ctx + (size_t)m0 * EMB, W + (size_t)n0 * EMB, acc, sh);

    const int tid = threadIdx.x, lane = tid & 31, wid = tid >> 5;
    const int g = lane >> 2, t = lane & 3;
    const int wy = wid >> 2, wx = wid & 3;
    #pragma unroll
    for (int mt = 0; mt < 4; mt++) {
        #pragma unroll
        for (int nt = 0; nt < 4; nt++) {
            int n = n0 + 32 * wx + 8 * nt + 2 * t;
            float bb0 = bias[n], bb1 = bias[n + 1];
            int row = m0 + 64 * wy + 16 * mt + g;
            *(float2*)&out[(size_t)row * EMB + n] =
                make_float2(acc[mt][nt][0] + bb0, acc[mt][nt][1] + bb1);
            *(float2*)&out[(size_t)(row + 8) * EMB + n] =
                make_float2(acc[mt][nt][2] + bb0, acc[mt][nt][3] + bb1);
        }
    }
}

// ============================================================================
// Kernel B: flash attention, tf32 mma.  grid (16, 24), 256 thr, 2 CTA/SM.
// Inputs arrive tf32-prerounded -> inner loops are pure LDS -> MMA.
// Warp w owns q-rows [16w,16w+16); raw scores streamed to wraw; m/l saved
// to g_m/g_l for the separate full-occupancy normalize kernel.
// Pads: Q/K/P = 68, V = 72 (conflict-free for their access patterns).
// ============================================================================
#define QPAD 68
#define KPAD 68
#define VPAD 72
#define PPAD 68
#define FLASH_SMEM ((128*QPAD + 64*KPAD + 64*VPAD + 128*PPAD) * 4)   // 105472 B

__global__ __launch_bounds__(256, 2) void flash_tc(float* __restrict__ wraw)
{
    extern __shared__ float sh[];
    float* Qs = sh;                          // [128][QPAD] tf32 bits
    float* Ks = Qs + 128 * QPAD;             // [64][KPAD]  tf32 bits
    float* Vs = Ks + 64 * KPAD;              // [64][VPAD]  tf32 bits
    float* Ps = Vs + 64 * VPAD;              // [128][PPAD] per-warp P tiles

    const int tid = threadIdx.x, lane = tid & 31, wid = tid >> 5;
    const int g = lane >> 2, t = lane & 3;
    const int hn = blockIdx.y;               // flattened head
    const int q0 = blockIdx.x * 128;

    const float* Qb = g_Qh + ((size_t)hn * S_LEN + q0) * HD;
    const float* Kb = g_Kh + (size_t)hn * S_LEN * HD;
    const float* Vb = g_Vh + (size_t)hn * S_LEN * HD;

    // preamble: stage Q, K0, V0 (already tf32 bits in gmem)
    #pragma unroll
    for (int i = 0; i < 8; i++) {
        int idx = tid + 256 * i; int row = idx >> 4, c4 = (idx & 15) * 4;
        cpa16(sm_addr(&Qs[row * QPAD + c4]), Qb + (size_t)row * HD + c4);
    }
    #pragma unroll
    for (int i = 0; i < 4; i++) {
        int idx = tid + 256 * i; int row = idx >> 4, c4 = (idx & 15) * 4;
        cpa16(sm_addr(&Ks[row * KPAD + c4]), Kb + (size_t)row * HD + c4);
        cpa16(sm_addr(&Vs[row * VPAD + c4]), Vb + (size_t)row * HD + c4);
    }
    CP_COMMIT();
    CP_WAIT0();

    float m0 = -INFINITY, m1 = -INFINITY, l0 = 0.f, l1 = 0.f;
    float oa[8][4] = {};
    const int qr = 16 * wid + g;             // warp-local base row (second = qr+8)
    float* Pw = Ps + wid * 16 * PPAD;        // per-warp P tile

    for (int kt = 0; kt < 32; kt++) {
        __syncthreads();                     // kt=0: preamble visible; kt>0: tail pair
        if (kt) { CP_WAIT0(); __syncthreads(); }   // K(kt), V(kt) landed + visible

        // ---- S = Q @ K^T / 8 ----
        float sa[8][4] = {};
        #pragma unroll
        for (int k8 = 0; k8 < 8; k8++) {
            int ra = qr * QPAD + 8 * k8;
            unsigned a0 = __float_as_uint(Qs[ra + t]);
            unsigned a1 = __float_as_uint(Qs[ra + 8 * QPAD + t]);
            unsigned a2 = __float_as_uint(Qs[ra + t + 4]);
            unsigned a3 = __float_as_uint(Qs[ra + 8 * QPAD + t + 4]);
            #pragma unroll
            for (int nt = 0; nt < 8; nt++) {
                int rb = (8 * nt + g) * KPAD + 8 * k8;
                mma_tf(sa[nt], a0, a1, a2, a3,
                       __float_as_uint(Ks[rb + t]),
                       __float_as_uint(Ks[rb + t + 4]));
            }
        }
        #pragma unroll
        for (int nt = 0; nt < 8; nt++) {
            sa[nt][0] *= 0.125f; sa[nt][1] *= 0.125f;
            sa[nt][2] *= 0.125f; sa[nt][3] *= 0.125f;
        }

        __syncthreads();                     // all warps done reading Ks
        if (kt < 31) {                       // prefetch K(kt+1) under softmax+PV
            #pragma unroll
            for (int i = 0; i < 4; i++) {
                int idx = tid + 256 * i; int row = idx >> 4, c4 = (idx & 15) * 4;
                cpa16(sm_addr(&Ks[row * KPAD + c4]),
                      Kb + (size_t)((kt + 1) * 64 + row) * HD + c4);
            }
            CP_COMMIT();
        }

        // ---- raw scores -> weights region (C layout: cols 2t,2t+1) ----
        if (wraw) {
            size_t rb0 = ((size_t)hn * S_LEN + (q0 + qr)) * S_LEN + (size_t)kt * 64 + 2 * t;
            #pragma unroll
            for (int nt = 0; nt < 8; nt++) {
                *(float2*)&wraw[rb0 + 8 * nt] = make_float2(sa[nt][0], sa[nt][1]);
                *(float2*)&wraw[rb0 + 8 * nt + 8 * (size_t)S_LEN] =
                    make_float2(sa[nt][2], sa[nt][3]);
            }
        }

        // ---- online softmax (row qr via c0/c1, row qr+8 via c2/c3) ----
        float lm0 = -INFINITY, lm1 = -INFINITY;
        #pragma unroll
        for (int nt = 0; nt < 8; nt++) {
            lm0 = fmaxf(lm0, fmaxf(sa[nt][0], sa[nt][1]));
            lm1 = fmaxf(lm1, fmaxf(sa[nt][2], sa[nt][3]));
        }
        lm0 = fmaxf(lm0, __shfl_xor_sync(0xffffffffu, lm0, 1));
        lm0 = fmaxf(lm0, __shfl_xor_sync(0xffffffffu, lm0, 2));
        lm1 = fmaxf(lm1, __shfl_xor_sync(0xffffffffu, lm1, 1));
        lm1 = fmaxf(lm1, __shfl_xor_sync(0xffffffffu, lm1, 2));
        float nm0 = fmaxf(m0, lm0), nm1 = fmaxf(m1, lm1);
        float ts0 = 0.f, ts1 = 0.f;
        #pragma unroll
        for (int nt = 0; nt < 8; nt++) {
            float p0 = __expf(sa[nt][0] - nm0);
            float p1 = __expf(sa[nt][1] - nm0);
            float p2 = __expf(sa[nt][2] - nm1);
            float p3 = __expf(sa[nt][3] - nm1);
            ts0 += p0 + p1; ts1 += p2 + p3;
            sa[nt][0] = f2tf_f(p0);          // tf32 bits, C layout
            sa[nt][1] = f2tf_f(p1);
            sa[nt][2] = f2tf_f(p2);
            sa[nt][3] = f2tf_f(p3);
        }
        ts0 += __shfl_xor_sync(0xffffffffu, ts0, 1);
        ts0 += __shfl_xor_sync(0xffffffffu, ts0, 2);
        ts1 += __shfl_xor_sync(0xffffffffu, ts1, 1);
        ts1 += __shfl_xor_sync(0xffffffffu, ts1, 2);
        float sc0 = __expf(m0 - nm0), sc1 = __expf(m1 - nm1);
        l0 = l0 * sc0 + ts0; l1 = l1 * sc1 + ts1;
        m0 = nm0; m1 = nm1;
        #pragma unroll
        for (int nt = 0; nt < 8; nt++) {
            oa[nt][0] *= sc0; oa[nt][1] *= sc0;
            oa[nt][2] *= sc1; oa[nt][3] *= sc1;
        }

        // ---- P: C-layout store to per-warp tile, A-layout reload ----
        #pragma unroll
        for (int nt = 0; nt < 8; nt++) {
            *(float2*)&Pw[g * PPAD + 8 * nt + 2 * t] =
                make_float2(sa[nt][0], sa[nt][1]);
            *(float2*)&Pw[(g + 8) * PPAD + 8 * nt + 2 * t] =
                make_float2(sa[nt][2], sa[nt][3]);
        }
        __syncwarp();

        // ---- O += P @ V ----
        #pragma unroll
        for (int k8 = 0; k8 < 8; k8++) {
            int pa = g * PPAD + 8 * k8;
            unsigned a0 = __float_as_uint(Pw[pa + t]);
            unsigned a1 = __float_as_uint(Pw[pa + 8 * PPAD + t]);
            unsigned a2 = __float_as_uint(Pw[pa + t + 4]);
            unsigned a3 = __float_as_uint(Pw[pa + t + 4 + 8 * PPAD]);
            #pragma unroll
            for (int nt = 0; nt < 8; nt++) {
                int vb = (8 * k8 + t) * VPAD + 8 * nt + g;
                mma_tf(oa[nt], a0, a1, a2, a3,
                       __float_as_uint(Vs[vb]),
                       __float_as_uint(Vs[vb + 4 * VPAD]));
            }
        }
        __syncthreads();                     // all warps done reading Vs
        if (kt < 31) {                       // prefetch V(kt+1)
            #pragma unroll
            for (int i = 0; i < 4; i++) {
                int idx = tid + 256 * i; int row = idx >> 4, c4 = (idx & 15) * 4;
                cpa16(sm_addr(&Vs[row * VPAD + c4]),
                      Vb + (size_t)((kt + 1) * 64 + row) * HD + c4);
            }
            CP_COMMIT();
        }
    }

    // epilogue: normalize, scatter ctx to [S,B,E], save (m,l) for norm kernel
    float inv0 = 1.f / l0, inv1 = 1.f / l1;
    const int r0 = q0 + qr, r1 = r0 + 8;
    const int bI = hn / NHEAD, hI = hn % NHEAD;
    #pragma unroll
    for (int nt = 0; nt < 8; nt++) {
        int d0 = 8 * nt + 2 * t;
        *(float2*)&g_ctx[((size_t)r0 * BATCH + bI) * EMB + hI * HD + d0] =
            make_float2(oa[nt][0] * inv0, oa[nt][1] * inv0);
        *(float2*)&g_ctx[((size_t)r1 * BATCH + bI) * EMB + hI * HD + d0] =
            make_float2(oa[nt][2] * inv1, oa[nt][3] * inv1);
    }
    if (t == 0) {
        g_m[hn * S_LEN + r0] = m0; g_m[hn * S_LEN + r1] = m1;
        g_l[hn * S_LEN + r0] = l0; g_l[hn * S_LEN + r1] = l1;
    }
}

// ============================================================================
// Kernel C: normalize raw scores in place: w = exp(s - m[row]) / l[row].
// Zero smem, full occupancy, one float4 per thread (measured ~134us).
// ============================================================================
__global__ __launch_bounds__(256) void softmax_norm_kernel(float* __restrict__ w)
{
    size_t i4 = (size_t)blockIdx.x * blockDim.x + threadIdx.x;
    size_t row = i4 / (S_LEN / 4);
    float m = g_m[row];
    float inv = 1.f / g_l[row];
    float4* wv = (float4*)w + i4;
    float4 v = *wv;
    v.x = __expf(v.x - m) * inv;
    v.y = __expf(v.y - m) * inv;
    v.z = __expf(v.z - m) * inv;
    v.w = __expf(v.w - m) * inv;
    *wv = v;
}

// ============================================================================
extern "C" void kernel_launch(void* const* d_in, const int* in_sizes, int n_in,
                              void* d_out, int out_size)
{
    const float* q   = (const float*)d_in[0];
    const float* k   = (const float*)d_in[1];
    const float* v   = (const float*)d_in[2];
    const float* W_Q = (const float*)d_in[3];
    const float* W_K = (const float*)d_in[4];
    const float* W_V = (const float*)d_in[5];
    const float* b_Q = (const float*)d_in[6];
    const float* b_K = (const float*)d_in[7];
    const float* b_V = (const float*)d_in[8];
    const float* W_O = (const float*)d_in[9];
    const float* b_O = (const float*)d_in[10];
    float* out = (float*)d_out;

    const long long NW_LL = (long long)NH * S_LEN * S_LEN;  // 100663296
    const long long total = (long long)OUT0 + NW_LL;
    float* wraw = ((long long)out_size >= total) ? (out + OUT0) : nullptr;

    cudaFuncSetAttribute(qkv_gemm,
                         cudaFuncAttributeMaxDynamicSharedMemorySize, PROJ_SMEM);
    cudaFuncSetAttribute(out_gemm,
                         cudaFuncAttributeMaxDynamicSharedMemorySize, PROJ_SMEM);
    cudaFuncSetAttribute(flash_tc,
                         cudaFuncAttributeMaxDynamicSharedMemorySize, FLASH_SMEM);

    dim3 gQKV(M_ROWS / 128, EMB / 128, 3);   // 32 x 6 x 3
    qkv_gemm<<<gQKV, 256, PROJ_SMEM>>>(q, k, v, W_Q, W_K, W_V, b_Q, b_K, b_V);

    dim3 gB(S_LEN / 128, NH);                // 16 x 24
    flash_tc<<<gB, 256, FLASH_SMEM>>>(wraw);

    if (wraw) {
        long long n4 = NW_LL / 4;            // 25165824 float4s
        int blocks = (int)(n4 / 256);        // 98304
        softmax_norm_kernel<<<blocks, 256>>>(wraw);
    }

    dim3 gO(M_ROWS / 128, EMB / 128);        // 32 x 6
    out_gemm<<<gO, 256, PROJ_SMEM>>>(W_O, b_O, out);
}

// round 15
// speedup vs baseline: 1.2149x; 1.0147x over previous
#include <cuda_runtime.h>
#include <math.h>

// Problem constants
#define S_LEN  2048
#define BATCH  2
#define EMB    768
#define NHEAD  12
#define HD     64
#define NH     (BATCH*NHEAD)        // 24 flattened heads
#define M_ROWS (S_LEN*BATCH)        // 4096
#define OUT0   (S_LEN*BATCH*EMB)    // 3145728 floats (output tensor)

// ---------------- device scratch (static, allocation-free) ----------------
// Qh/Kh/Vh hold tf32-prerounded values in MMA-FRAGMENT-MAJOR tile layouts:
//  per (head, 64-row tile) of 4096 floats:
//   Q tile: [k8][rgrp][lane] float2 = {Q[8rgrp+g][8k8+t], Q[..][8k8+t+4]}
//   K tile: [k4][nt][lane] float4 = K[8nt+g][16k4 + t + {0,4,8,12}]
//   V tile: [k4][nt][lane] float4 = V[16k4 + t + {0,4,8,12}][8nt+g]
//  (lane = 4g+t; g=lane>>2, t=lane&3)
__device__ float g_Qh[NH * S_LEN * HD];
__device__ float g_Kh[NH * S_LEN * HD];
__device__ float g_Vh[NH * S_LEN * HD];
__device__ float g_ctx[M_ROWS * EMB];     // attn_output in [S,B,E] layout (full fp32)
__device__ float g_m[NH * S_LEN];         // per-row softmax max
__device__ float g_l[NH * S_LEN];         // per-row softmax sum

// ============================================================================
// portable (compute_103-safe) helpers
// tf32 m16n8k8 fragment layouts (PTX ISA):
//  A (16x8):  a0=(g, t)  a1=(g+8, t)  a2=(g, t+4)  a3=(g+8, t+4)
//  B (8x8):   b0=(k=t, n=g)  b1=(k=t+4, n=g)
//  C (16x8):  c0=(g, 2t) c1=(g, 2t+1) c2=(g+8, 2t) c3=(g+8, 2t+1)
// ============================================================================
__device__ __forceinline__ unsigned sm_addr(const void* p) {
    unsigned a;
    asm("{ .reg .u64 t; cvta.to.shared.u64 t, %1; cvt.u32.u64 %0, t; }" : "=r"(a) : "l"(p));
    return a;
}
__device__ __forceinline__ unsigned f2tf(float x) {
    unsigned r;
    asm("cvt.rna.tf32.f32 %0, %1;" : "=r"(r) : "f"(x));
    return r;
}
__device__ __forceinline__ float f2tf_f(float x) { return __uint_as_float(f2tf(x)); }

__device__ __forceinline__ void mma_tf(float c[4], unsigned a0, unsigned a1,
                                       unsigned a2, unsigned a3,
                                       unsigned b0, unsigned b1) {
    asm volatile(
        "mma.sync.aligned.m16n8k8.row.col.f32.tf32.tf32.f32 "
        "{%0,%1,%2,%3}, {%4,%5,%6,%7}, {%8,%9}, {%0,%1,%2,%3};"
        : "+f"(c[0]), "+f"(c[1]), "+f"(c[2]), "+f"(c[3])
        : "r"(a0), "r"(a1), "r"(a2), "r"(a3), "r"(b0), "r"(b1));
}
__device__ __forceinline__ void cpa16(unsigned saddr, const void* gptr) {
    asm volatile("cp.async.cg.shared.global [%0], [%1], 16;" :: "r"(saddr), "l"(gptr));
}
#define CP_COMMIT()  asm volatile("cp.async.commit_group;")
#define CP_WAIT0()   asm volatile("cp.async.wait_group 0;")
#define CP_WAIT1()   asm volatile("cp.async.wait_group 1;")

// ============================================================================
// Projection GEMM core (unchanged from R14): 3-stage cp.async pipeline,
// in-smem tf32 conversion. C[128x128] = A[128x768] @ B[128x768]^T.
// ============================================================================
#define PLD 36
#define PBUF (128 * PLD)
#define PROJ_SMEM (6 * PBUF * 4)         // 110592 B

__device__ __forceinline__ void proj_core(const float* __restrict__ Ag,
                                          const float* __restrict__ Bg,
                                          float (&acc)[4][4][4], float* sh)
{
    float* Ab[3] = { sh,            sh + PBUF,     sh + 2 * PBUF };
    float* Bb[3] = { sh + 3 * PBUF, sh + 4 * PBUF, sh + 5 * PBUF };
    const int tid = threadIdx.x;
    const int lane = tid & 31, wid = tid >> 5;
    const int g = lane >> 2, t = lane & 3;
    const int wy = wid >> 2, wx = wid & 3;

    auto stage = [&](int c, int bs) {
        #pragma unroll
        for (int i = 0; i < 4; i++) {
            int idx = tid + 256 * i;
            int row = idx >> 3, c4 = (idx & 7) * 4;
            cpa16(sm_addr(&Ab[bs][row * PLD + c4]), Ag + (size_t)row * EMB + c * 32 + c4);
            cpa16(sm_addr(&Bb[bs][row * PLD + c4]), Bg + (size_t)row * EMB + c * 32 + c4);
        }
        CP_COMMIT();
    };
    auto convert = [&](int bs) {
        #pragma unroll
        for (int i = 0; i < 4; i++) {
            int idx = tid + 256 * i;
            int row = idx >> 3, c4 = (idx & 7) * 4;
            float4* pa = (float4*)&Ab[bs][row * PLD + c4];
            float4 va = *pa;
            va.x = f2tf_f(va.x); va.y = f2tf_f(va.y);
            va.z = f2tf_f(va.z); va.w = f2tf_f(va.w);
            *pa = va;
            float4* pb = (float4*)&Bb[bs][row * PLD + c4];
            float4 vb = *pb;
            vb.x = f2tf_f(vb.x); vb.y = f2tf_f(vb.y);
            vb.z = f2tf_f(vb.z); vb.w = f2tf_f(vb.w);
            *pb = vb;
        }
    };

    stage(0, 0);
    stage(1, 1);
    for (int c = 0; c < 24; c++) {
        if (c < 23) { CP_WAIT1(); } else { CP_WAIT0(); }
        __syncthreads();
        convert(c % 3);
        __syncthreads();

        const float* Af = Ab[c % 3];
        const float* Bf = Bb[c % 3];
        #pragma unroll
        for (int ks = 0; ks < 4; ks++) {
            const int k0s = 8 * ks;
            unsigned a[4][4];
            #pragma unroll
            for (int mt = 0; mt < 4; mt++) {
                int ra = (64 * wy + 16 * mt + g) * PLD + k0s;
                a[mt][0] = __float_as_uint(Af[ra + t]);
                a[mt][1] = __float_as_uint(Af[ra + 8 * PLD + t]);
                a[mt][2] = __float_as_uint(Af[ra + t + 4]);
                a[mt][3] = __float_as_uint(Af[ra + 8 * PLD + t + 4]);
            }
            #pragma unroll
            for (int nt = 0; nt < 4; nt++) {
                int rb = (32 * wx + 8 * nt + g) * PLD + k0s;
                unsigned b0 = __float_as_uint(Bf[rb + t]);
                unsigned b1 = __float_as_uint(Bf[rb + t + 4]);
                #pragma unroll
                for (int mt = 0; mt < 4; mt++)
                    mma_tf(acc[mt][nt], a[mt][0], a[mt][1], a[mt][2], a[mt][3], b0, b1);
            }
        }
        if (c + 2 < 24) stage(c + 2, (c + 2) % 3);
    }
}

// ============================================================================
// Kernel A: fused QKV projection; epilogue scatters tf32-prerounded values
// into the FRAGMENT-MAJOR tile layouts consumed by flash.
// ============================================================================
__global__ __launch_bounds__(256, 2) void qkv_gemm(
    const float* __restrict__ q, const float* __restrict__ k, const float* __restrict__ v,
    const float* __restrict__ WQ, const float* __restrict__ WK, const float* __restrict__ WV,
    const float* __restrict__ bQ, const float* __restrict__ bK, const float* __restrict__ bV)
{
    extern __shared__ float sh[];
    const int m0 = blockIdx.x * 128, n0 = blockIdx.y * 128, sel = blockIdx.z;
    const float* X    = (sel == 0) ? q  : (sel == 1) ? k  : v;
    const float* W    = (sel == 0) ? WQ : (sel == 1) ? WK : WV;
    const float* bias = (sel == 0) ? bQ : (sel == 1) ? bK : bV;
    float* dst        = (sel == 0) ? g_Qh : (sel == 1) ? g_Kh : g_Vh;

    float acc[4][4][4] = {};
    proj_core(X + (size_t)m0 * EMB, W + (size_t)n0 * EMB, acc, sh);

    const int tid = threadIdx.x, lane = tid & 31, wid = tid >> 5;
    const int g = lane >> 2, t = lane & 3;
    const int wy = wid >> 2, wx = wid & 3;

    #pragma unroll
    for (int mt = 0; mt < 4; mt++) {
        #pragma unroll
        for (int nt = 0; nt < 4; nt++) {
            int n = n0 + 32 * wx + 8 * nt + 2 * t;    // cols n, n+1
            int h = n >> 6;
            int row = m0 + 64 * wy + 16 * mt + g;     // rows row, row+8
            float bb0 = bias[n], bb1 = bias[n + 1];
            float vals[2][2] = {
                { f2tf_f(acc[mt][nt][0] + bb0), f2tf_f(acc[mt][nt][1] + bb1) },
                { f2tf_f(acc[mt][nt][2] + bb0), f2tf_f(acc[mt][nt][3] + bb1) } };
            #pragma unroll
            for (int rr = 0; rr < 2; rr++) {
                int R = row + 8 * rr;
                int s = R >> 1, bI = R & 1;
                int hn = bI * NHEAD + h;
                int t64 = s >> 6, loc = s & 63;
                size_t base = ((size_t)hn * 32 + t64) * 4096;
                #pragma unroll
                for (int dd = 0; dd < 2; dd++) {
                    int D = (n & 63) + dd;
                    size_t off;
                    if (sel == 0) {        // Q: [k8][rgrp][lane] float2 + j
                        off = base + ((size_t)(((D >> 3) * 8 + (loc >> 3)) * 32
                               + 4 * (loc & 7) + (D & 3)) << 1) + ((D >> 2) & 1);
                    } else if (sel == 1) { // K: [k4][nt][lane] float4 + c
                        off = base + ((size_t)(((D >> 4) * 8 + (loc >> 3)) * 32
                               + 4 * (loc & 7) + (D & 3)) << 2) + ((D >> 2) & 3);
                    } else {               // V: [k4][nt][lane] float4 + c (k from loc)
                        off = base + ((size_t)(((loc >> 4) * 8 + (D >> 3)) * 32
                               + 4 * (D & 7) + (loc & 3)) << 2) + ((loc >> 2) & 3);
                    }
                    dst[off] = vals[rr][dd];
                }
            }
        }
    }
}

// ============================================================================
// Kernel D: output projection (unchanged; 192 blocks, 2 CTA/SM).
// ============================================================================
__global__ __launch_bounds__(256, 2) void out_gemm(
    const float* __restrict__ W, const float* __restrict__ bias, float* __restrict__ out)
{
    extern __shared__ float sh[];
    const int m0 = blockIdx.x * 128, n0 = blockIdx.y * 128;

    float acc[4][4][4] = {};
    proj_core(g_ctx + (size_t)m0 * EMB, W + (size_t)n0 * EMB, acc, sh);

    const int tid = threadIdx.x, lane = tid & 31, wid = tid >> 5;
    const int g = lane >> 2, t = lane & 3;
    const int wy = wid >> 2, wx = wid & 3;
    #pragma unroll
    for (int mt = 0; mt < 4; mt++) {
        #pragma unroll
        for (int nt = 0; nt < 4; nt++) {
            int n = n0 + 32 * wx + 8 * nt + 2 * t;
            float bb0 = bias[n], bb1 = bias[n + 1];
            int row = m0 + 64 * wy + 16 * mt + g;
            *(float2*)&out[(size_t)row * EMB + n] =
                make_float2(acc[mt][nt][0] + bb0, acc[mt][nt][1] + bb1);
            *(float2*)&out[(size_t)(row + 8) * EMB + n] =
                make_float2(acc[mt][nt][2] + bb0, acc[mt][nt][3] + bb1);
        }
    }
}

// ============================================================================
// Kernel B: flash attention with fragment-major operands.
// grid (16, 24), 256 thr, 2 CTA/SM. All K/V/Q operand loads are wide LDS from
// unpadded, lane-consecutive fragment tiles (conflict-free by construction).
// Smem: Q 2 tiles (32KB) + K tile (16KB) + V tile (16KB) + P (34KB) = 98KB.
// ============================================================================
#define PPAD 68
#define FLASH_SMEM ((8192 + 4096 + 4096 + 128 * PPAD) * 4)   // 100352 B

__global__ __launch_bounds__(256, 2) void flash_tc(float* __restrict__ wraw)
{
    extern __shared__ float sh[];
    float* Qs = sh;                          // 2 fragment tiles (8192 floats)
    float* Ks = Qs + 8192;                   // 1 fragment tile (4096)
    float* Vs = Ks + 4096;                   // 1 fragment tile (4096)
    float* Ps = Vs + 4096;                   // [128][PPAD] per-warp P tiles

    const int tid = threadIdx.x, lane = tid & 31, wid = tid >> 5;
    const int g = lane >> 2, t = lane & 3;
    const int hn = blockIdx.y;
    const int q0 = blockIdx.x * 128;

    const float* Qb = g_Qh + ((size_t)hn * 32 + 2 * blockIdx.x) * 4096;  // 2 tiles
    const float* Kb = g_Kh + (size_t)hn * 32 * 4096;
    const float* Vb = g_Vh + (size_t)hn * 32 * 4096;

    // preamble: stage Q (2 tiles), K0, V0 — contiguous float4 copies
    #pragma unroll
    for (int i = 0; i < 8; i++) {
        int idx = tid + 256 * i;
        cpa16(sm_addr(&Qs[idx * 4]), Qb + (size_t)idx * 4);
    }
    #pragma unroll
    for (int i = 0; i < 4; i++) {
        int idx = tid + 256 * i;
        cpa16(sm_addr(&Ks[idx * 4]), Kb + (size_t)idx * 4);
        cpa16(sm_addr(&Vs[idx * 4]), Vb + (size_t)idx * 4);
    }
    CP_COMMIT();
    CP_WAIT0();

    float m0 = -INFINITY, m1 = -INFINITY, l0 = 0.f, l1 = 0.f;
    float oa[8][4] = {};
    const int qr = 16 * wid + g;             // block-local base row (second = qr+8)
    const float* Qw = Qs + (wid >> 2) * 4096;
    const int wl2 = (wid & 3) * 2;           // rgrp base within the warp's Q tile
    float* Pw = Ps + wid * 16 * PPAD;

    for (int kt = 0; kt < 32; kt++) {
        __syncthreads();
        if (kt) { CP_WAIT0(); __syncthreads(); }   // K(kt), V(kt) landed + visible

        // ---- S = Q @ K^T / 8 ----
        float sa[8][4] = {};
        #pragma unroll
        for (int k4 = 0; k4 < 4; k4++) {
            int k8a = 2 * k4, k8b = k8a + 1;
            float2 qa0 = *(const float2*)&Qw[((k8a * 8 + wl2) * 32 + lane) * 2];
            float2 qa1 = *(const float2*)&Qw[((k8a * 8 + wl2 + 1) * 32 + lane) * 2];
            float2 qb0 = *(const float2*)&Qw[((k8b * 8 + wl2) * 32 + lane) * 2];
            float2 qb1 = *(const float2*)&Qw[((k8b * 8 + wl2 + 1) * 32 + lane) * 2];
            unsigned A0a = __float_as_uint(qa0.x), A1a = __float_as_uint(qa1.x);
            unsigned A2a = __float_as_uint(qa0.y), A3a = __float_as_uint(qa1.y);
            unsigned A0b = __float_as_uint(qb0.x), A1b = __float_as_uint(qb1.x);
            unsigned A2b = __float_as_uint(qb0.y), A3b = __float_as_uint(qb1.y);
            #pragma unroll
            for (int nt = 0; nt < 8; nt++) {
                float4 kv = *(const float4*)&Ks[((k4 * 8 + nt) * 32 + lane) * 4];
                mma_tf(sa[nt], A0a, A1a, A2a, A3a,
                       __float_as_uint(kv.x), __float_as_uint(kv.y));
                mma_tf(sa[nt], A0b, A1b, A2b, A3b,
                       __float_as_uint(kv.z), __float_as_uint(kv.w));
            }
        }
        #pragma unroll
        for (int nt = 0; nt < 8; nt++) {
            sa[nt][0] *= 0.125f; sa[nt][1] *= 0.125f;
            sa[nt][2] *= 0.125f; sa[nt][3] *= 0.125f;
        }

        __syncthreads();                     // all warps done reading Ks
        if (kt < 31) {                       // prefetch K(kt+1)
            const float* src = Kb + (size_t)(kt + 1) * 4096;
            #pragma unroll
            for (int i = 0; i < 4; i++) {
                int idx = tid + 256 * i;
                cpa16(sm_addr(&Ks[idx * 4]), src + (size_t)idx * 4);
            }
            CP_COMMIT();
        }

        // ---- raw scores -> weights region (C layout: cols 2t,2t+1) ----
        if (wraw) {
            size_t rb0 = ((size_t)hn * S_LEN + (q0 + qr)) * S_LEN + (size_t)kt * 64 + 2 * t;
            #pragma unroll
            for (int nt = 0; nt < 8; nt++) {
                *(float2*)&wraw[rb0 + 8 * nt] = make_float2(sa[nt][0], sa[nt][1]);
                *(float2*)&wraw[rb0 + 8 * nt + 8 * (size_t)S_LEN] =
                    make_float2(sa[nt][2], sa[nt][3]);
            }
        }

        // ---- online softmax ----
        float lm0 = -INFINITY, lm1 = -INFINITY;
        #pragma unroll
        for (int nt = 0; nt < 8; nt++) {
            lm0 = fmaxf(lm0, fmaxf(sa[nt][0], sa[nt][1]));
            lm1 = fmaxf(lm1, fmaxf(sa[nt][2], sa[nt][3]));
        }
        lm0 = fmaxf(lm0, __shfl_xor_sync(0xffffffffu, lm0, 1));
        lm0 = fmaxf(lm0, __shfl_xor_sync(0xffffffffu, lm0, 2));
        lm1 = fmaxf(lm1, __shfl_xor_sync(0xffffffffu, lm1, 1));
        lm1 = fmaxf(lm1, __shfl_xor_sync(0xffffffffu, lm1, 2));
        float nm0 = fmaxf(m0, lm0), nm1 = fmaxf(m1, lm1);
        float ts0 = 0.f, ts1 = 0.f;
        #pragma unroll
        for (int nt = 0; nt < 8; nt++) {
            float p0 = __expf(sa[nt][0] - nm0);
            float p1 = __expf(sa[nt][1] - nm0);
            float p2 = __expf(sa[nt][2] - nm1);
            float p3 = __expf(sa[nt][3] - nm1);
            ts0 += p0 + p1; ts1 += p2 + p3;
            sa[nt][0] = f2tf_f(p0);
            sa[nt][1] = f2tf_f(p1);
            sa[nt][2] = f2tf_f(p2);
            sa[nt][3] = f2tf_f(p3);
        }
        ts0 += __shfl_xor_sync(0xffffffffu, ts0, 1);
        ts0 += __shfl_xor_sync(0xffffffffu, ts0, 2);
        ts1 += __shfl_xor_sync(0xffffffffu, ts1, 1);
        ts1 += __shfl_xor_sync(0xffffffffu, ts1, 2);
        float sc0 = __expf(m0 - nm0), sc1 = __expf(m1 - nm1);
        l0 = l0 * sc0 + ts0; l1 = l1 * sc1 + ts1;
        m0 = nm0; m1 = nm1;
        #pragma unroll
        for (int nt = 0; nt < 8; nt++) {
            oa[nt][0] *= sc0; oa[nt][1] *= sc0;
            oa[nt][2] *= sc1; oa[nt][3] *= sc1;
        }

        // ---- P: C-layout store to per-warp tile, A-layout reload ----
        #pragma unroll
        for (int nt = 0; nt < 8; nt++) {
            *(float2*)&Pw[g * PPAD + 8 * nt + 2 * t] =
                make_float2(sa[nt][0], sa[nt][1]);
            *(float2*)&Pw[(g + 8) * PPAD + 8 * nt + 2 * t] =
                make_float2(sa[nt][2], sa[nt][3]);
        }
        __syncwarp();

        // ---- O += P @ V  (V from fragment tile, 2 mma per LDS.128) ----
        #pragma unroll
        for (int k4 = 0; k4 < 4; k4++) {
            int k8a = 2 * k4, k8b = k8a + 1;
            int paA = g * PPAD + 8 * k8a;
            unsigned A0a = __float_as_uint(Pw[paA + t]);
            unsigned A1a = __float_as_uint(Pw[paA + 8 * PPAD + t]);
            unsigned A2a = __float_as_uint(Pw[paA + t + 4]);
            unsigned A3a = __float_as_uint(Pw[paA + t + 4 + 8 * PPAD]);
            int paB = g * PPAD + 8 * k8b;
            unsigned A0b = __float_as_uint(Pw[paB + t]);
            unsigned A1b = __float_as_uint(Pw[paB + 8 * PPAD + t]);
            unsigned A2b = __float_as_uint(Pw[paB + t + 4]);
            unsigned A3b = __float_as_uint(Pw[paB + t + 4 + 8 * PPAD]);
            #pragma unroll
            for (int nt = 0; nt < 8; nt++) {
                float4 vv = *(const float4*)&Vs[((k4 * 8 + nt) * 32 + lane) * 4];
                mma_tf(oa[nt], A0a, A1a, A2a, A3a,
                       __float_as_uint(vv.x), __float_as_uint(vv.y));
                mma_tf(oa[nt], A0b, A1b, A2b, A3b,
                       __float_as_uint(vv.z), __float_as_uint(vv.w));
            }
        }
        __syncthreads();                     // all warps done reading Vs
        if (kt < 31) {                       // prefetch V(kt+1)
            const float* src = Vb + (size_t)(kt + 1) * 4096;
            #pragma unroll
            for (int i = 0; i < 4; i++) {
                int idx = tid + 256 * i;
                cpa16(sm_addr(&Vs[idx * 4]), src + (size_t)idx * 4);
            }
            CP_COMMIT();
        }
    }

    // epilogue: normalize, scatter ctx to [S,B,E], save (m,l) for norm kernel
    float inv0 = 1.f / l0, inv1 = 1.f / l1;
    const int r0 = q0 + qr, r1 = r0 + 8;
    const int bI = hn / NHEAD, hI = hn % NHEAD;
    #pragma unroll
    for (int nt = 0; nt < 8; nt++) {
        int d0 = 8 * nt + 2 * t;
        *(float2*)&g_ctx[((size_t)r0 * BATCH + bI) * EMB + hI * HD + d0] =
            make_float2(oa[nt][0] * inv0, oa[nt][1] * inv0);
        *(float2*)&g_ctx[((size_t)r1 * BATCH + bI) * EMB + hI * HD + d0] =
            make_float2(oa[nt][2] * inv1, oa[nt][3] * inv1);
    }
    if (t == 0) {
        g_m[hn * S_LEN + r0] = m0; g_m[hn * S_LEN + r1] = m1;
        g_l[hn * S_LEN + r0] = l0; g_l[hn * S_LEN + r1] = l1;
    }
}

// ============================================================================
// Kernel C: normalize raw scores in place: w = exp(s - m[row]) / l[row].
// Zero smem, full occupancy (measured ~134us, HBM roofline).
// ============================================================================
__global__ __launch_bounds__(256) void softmax_norm_kernel(float* __restrict__ w)
{
    size_t i4 = (size_t)blockIdx.x * blockDim.x + threadIdx.x;
    size_t row = i4 / (S_LEN / 4);
    float m = g_m[row];
    float inv = 1.f / g_l[row];
    float4* wv = (float4*)w + i4;
    float4 v = *wv;
    v.x = __expf(v.x - m) * inv;
    v.y = __expf(v.y - m) * inv;
    v.z = __expf(v.z - m) * inv;
    v.w = __expf(v.w - m) * inv;
    *wv = v;
}

// ============================================================================
extern "C" void kernel_launch(void* const* d_in, const int* in_sizes, int n_in,
                              void* d_out, int out_size)
{
    const float* q   = (const float*)d_in[0];
    const float* k   = (const float*)d_in[1];
    const float* v   = (const float*)d_in[2];
    const float* W_Q = (const float*)d_in[3];
    const float* W_K = (const float*)d_in[4];
    const float* W_V = (const float*)d_in[5];
    const float* b_Q = (const float*)d_in[6];
    const float* b_K = (const float*)d_in[7];
    const float* b_V = (const float*)d_in[8];
    const float* W_O = (const float*)d_in[9];
    const float* b_O = (const float*)d_in[10];
    float* out = (float*)d_out;

    const long long NW_LL = (long long)NH * S_LEN * S_LEN;  // 100663296
    const long long total = (long long)OUT0 + NW_LL;
    float* wraw = ((long long)out_size >= total) ? (out + OUT0) : nullptr;

    cudaFuncSetAttribute(qkv_gemm,
                         cudaFuncAttributeMaxDynamicSharedMemorySize, PROJ_SMEM);
    cudaFuncSetAttribute(out_gemm,
                         cudaFuncAttributeMaxDynamicSharedMemorySize, PROJ_SMEM);
    cudaFuncSetAttribute(flash_tc,
                         cudaFuncAttributeMaxDynamicSharedMemorySize, FLASH_SMEM);

    dim3 gQKV(M_ROWS / 128, EMB / 128, 3);   // 32 x 6 x 3
    qkv_gemm<<<gQKV, 256, PROJ_SMEM>>>(q, k, v, W_Q, W_K, W_V, b_Q, b_K, b_V);

    dim3 gB(S_LEN / 128, NH);                // 16 x 24
    flash_tc<<<gB, 256, FLASH_SMEM>>>(wraw);

    if (wraw) {
        long long n4 = NW_LL / 4;            // 25165824 float4s
        int blocks = (int)(n4 / 256);        // 98304
        softmax_norm_kernel<<<blocks, 256>>>(wraw);
    }

    dim3 gO(M_ROWS / 128, EMB / 128);        // 32 x 6
    out_gemm<<<gO, 256, PROJ_SMEM>>>(W_O, b_O, out);
}

// round 16
// speedup vs baseline: 1.2983x; 1.0686x over previous
#include <cuda_runtime.h>
#include <math.h>

// Problem constants
#define S_LEN  2048
#define BATCH  2
#define EMB    768
#define NHEAD  12
#define HD     64
#define NH     (BATCH*NHEAD)        // 24 flattened heads
#define M_ROWS (S_LEN*BATCH)        // 4096
#define OUT0   (S_LEN*BATCH*EMB)    // 3145728 floats (output tensor)

// ---------------- device scratch (static, allocation-free) ----------------
// Qh/Kh/Vh hold tf32-prerounded values in MMA-FRAGMENT-MAJOR tile layouts:
//  per (head, 64-row tile) of 4096 floats:
//   Q tile: [k8][rgrp][lane] float2 = {Q[8rgrp+g][8k8+t], Q[..][8k8+t+4]}
//   K tile: [k4][nt][lane] float4 = K[8nt+g][16k4 + t + {0,4,8,12}]
//   V tile: [k4][nt][lane] float4 = V[16k4 + t + {0,4,8,12}][8nt+g]
//  (lane = 4g+t; g=lane>>2, t=lane&3)
__device__ float g_Qh[NH * S_LEN * HD];
__device__ float g_Kh[NH * S_LEN * HD];
__device__ float g_Vh[NH * S_LEN * HD];
__device__ float g_ctx[M_ROWS * EMB];     // attn_output in [S,B,E] layout (full fp32)
__device__ float g_m[NH * S_LEN];         // per-row softmax max
__device__ float g_l[NH * S_LEN];         // per-row softmax sum

// ============================================================================
// portable (compute_103-safe) helpers
// tf32 m16n8k8 fragment layouts (PTX ISA):
//  A (16x8):  a0=(g, t)  a1=(g+8, t)  a2=(g, t+4)  a3=(g+8, t+4)
//  B (8x8):   b0=(k=t, n=g)  b1=(k=t+4, n=g)
//  C (16x8):  c0=(g, 2t) c1=(g, 2t+1) c2=(g+8, 2t) c3=(g+8, 2t+1)
// ============================================================================
__device__ __forceinline__ unsigned sm_addr(const void* p) {
    unsigned a;
    asm("{ .reg .u64 t; cvta.to.shared.u64 t, %1; cvt.u32.u64 %0, t; }" : "=r"(a) : "l"(p));
    return a;
}
__device__ __forceinline__ unsigned f2tf(float x) {
    unsigned r;
    asm("cvt.rna.tf32.f32 %0, %1;" : "=r"(r) : "f"(x));
    return r;
}
__device__ __forceinline__ float f2tf_f(float x) { return __uint_as_float(f2tf(x)); }

__device__ __forceinline__ void mma_tf(float c[4], unsigned a0, unsigned a1,
                                       unsigned a2, unsigned a3,
                                       unsigned b0, unsigned b1) {
    asm volatile(
        "mma.sync.aligned.m16n8k8.row.col.f32.tf32.tf32.f32 "
        "{%0,%1,%2,%3}, {%4,%5,%6,%7}, {%8,%9}, {%0,%1,%2,%3};"
        : "+f"(c[0]), "+f"(c[1]), "+f"(c[2]), "+f"(c[3])
        : "r"(a0), "r"(a1), "r"(a2), "r"(a3), "r"(b0), "r"(b1));
}
__device__ __forceinline__ void cpa16(unsigned saddr, const void* gptr) {
    asm volatile("cp.async.cg.shared.global [%0], [%1], 16;" :: "r"(saddr), "l"(gptr));
}
#define CP_COMMIT()  asm volatile("cp.async.commit_group;")
#define CP_WAIT0()   asm volatile("cp.async.wait_group 0;")
#define CP_WAIT1()   asm volatile("cp.async.wait_group 1;")

// ============================================================================
// Projection GEMM core (unchanged): 3-stage cp.async pipeline, in-smem tf32
// conversion. C[128x128] = A[128x768] @ B[128x768]^T.
// ============================================================================
#define PLD 36
#define PBUF (128 * PLD)
#define PROJ_SMEM (6 * PBUF * 4)         // 110592 B

__device__ __forceinline__ void proj_core(const float* __restrict__ Ag,
                                          const float* __restrict__ Bg,
                                          float (&acc)[4][4][4], float* sh)
{
    float* Ab[3] = { sh,            sh + PBUF,     sh + 2 * PBUF };
    float* Bb[3] = { sh + 3 * PBUF, sh + 4 * PBUF, sh + 5 * PBUF };
    const int tid = threadIdx.x;
    const int lane = tid & 31, wid = tid >> 5;
    const int g = lane >> 2, t = lane & 3;
    const int wy = wid >> 2, wx = wid & 3;

    auto stage = [&](int c, int bs) {
        #pragma unroll
        for (int i = 0; i < 4; i++) {
            int idx = tid + 256 * i;
            int row = idx >> 3, c4 = (idx & 7) * 4;
            cpa16(sm_addr(&Ab[bs][row * PLD + c4]), Ag + (size_t)row * EMB + c * 32 + c4);
            cpa16(sm_addr(&Bb[bs][row * PLD + c4]), Bg + (size_t)row * EMB + c * 32 + c4);
        }
        CP_COMMIT();
    };
    auto convert = [&](int bs) {
        #pragma unroll
        for (int i = 0; i < 4; i++) {
            int idx = tid + 256 * i;
            int row = idx >> 3, c4 = (idx & 7) * 4;
            float4* pa = (float4*)&Ab[bs][row * PLD + c4];
            float4 va = *pa;
            va.x = f2tf_f(va.x); va.y = f2tf_f(va.y);
            va.z = f2tf_f(va.z); va.w = f2tf_f(va.w);
            *pa = va;
            float4* pb = (float4*)&Bb[bs][row * PLD + c4];
            float4 vb = *pb;
            vb.x = f2tf_f(vb.x); vb.y = f2tf_f(vb.y);
            vb.z = f2tf_f(vb.z); vb.w = f2tf_f(vb.w);
            *pb = vb;
        }
    };

    stage(0, 0);
    stage(1, 1);
    for (int c = 0; c < 24; c++) {
        if (c < 23) { CP_WAIT1(); } else { CP_WAIT0(); }
        __syncthreads();
        convert(c % 3);
        __syncthreads();

        const float* Af = Ab[c % 3];
        const float* Bf = Bb[c % 3];
        #pragma unroll
        for (int ks = 0; ks < 4; ks++) {
            const int k0s = 8 * ks;
            unsigned a[4][4];
            #pragma unroll
            for (int mt = 0; mt < 4; mt++) {
                int ra = (64 * wy + 16 * mt + g) * PLD + k0s;
                a[mt][0] = __float_as_uint(Af[ra + t]);
                a[mt][1] = __float_as_uint(Af[ra + 8 * PLD + t]);
                a[mt][2] = __float_as_uint(Af[ra + t + 4]);
                a[mt][3] = __float_as_uint(Af[ra + 8 * PLD + t + 4]);
            }
            #pragma unroll
            for (int nt = 0; nt < 4; nt++) {
                int rb = (32 * wx + 8 * nt + g) * PLD + k0s;
                unsigned b0 = __float_as_uint(Bf[rb + t]);
                unsigned b1 = __float_as_uint(Bf[rb + t + 4]);
                #pragma unroll
                for (int mt = 0; mt < 4; mt++)
                    mma_tf(acc[mt][nt], a[mt][0], a[mt][1], a[mt][2], a[mt][3], b0, b1);
            }
        }
        if (c + 2 < 24) stage(c + 2, (c + 2) % 3);
    }
}

// ============================================================================
// Kernel A: fused QKV projection; epilogue scatters tf32-prerounded values
// into the FRAGMENT-MAJOR tile layouts consumed by flash.
// ============================================================================
__global__ __launch_bounds__(256, 2) void qkv_gemm(
    const float* __restrict__ q, const float* __restrict__ k, const float* __restrict__ v,
    const float* __restrict__ WQ, const float* __restrict__ WK, const float* __restrict__ WV,
    const float* __restrict__ bQ, const float* __restrict__ bK, const float* __restrict__ bV)
{
    extern __shared__ float sh[];
    const int m0 = blockIdx.x * 128, n0 = blockIdx.y * 128, sel = blockIdx.z;
    const float* X    = (sel == 0) ? q  : (sel == 1) ? k  : v;
    const float* W    = (sel == 0) ? WQ : (sel == 1) ? WK : WV;
    const float* bias = (sel == 0) ? bQ : (sel == 1) ? bK : bV;
    float* dst        = (sel == 0) ? g_Qh : (sel == 1) ? g_Kh : g_Vh;

    float acc[4][4][4] = {};
    proj_core(X + (size_t)m0 * EMB, W + (size_t)n0 * EMB, acc, sh);

    const int tid = threadIdx.x, lane = tid & 31, wid = tid >> 5;
    const int g = lane >> 2, t = lane & 3;
    const int wy = wid >> 2, wx = wid & 3;

    #pragma unroll
    for (int mt = 0; mt < 4; mt++) {
        #pragma unroll
        for (int nt = 0; nt < 4; nt++) {
            int n = n0 + 32 * wx + 8 * nt + 2 * t;    // cols n, n+1
            int h = n >> 6;
            int row = m0 + 64 * wy + 16 * mt + g;     // rows row, row+8
            float bb0 = bias[n], bb1 = bias[n + 1];
            float vals[2][2] = {
                { f2tf_f(acc[mt][nt][0] + bb0), f2tf_f(acc[mt][nt][1] + bb1) },
                { f2tf_f(acc[mt][nt][2] + bb0), f2tf_f(acc[mt][nt][3] + bb1) } };
            #pragma unroll
            for (int rr = 0; rr < 2; rr++) {
                int R = row + 8 * rr;
                int s = R >> 1, bI = R & 1;
                int hn = bI * NHEAD + h;
                int t64 = s >> 6, loc = s & 63;
                size_t base = ((size_t)hn * 32 + t64) * 4096;
                #pragma unroll
                for (int dd = 0; dd < 2; dd++) {
                    int D = (n & 63) + dd;
                    size_t off;
                    if (sel == 0) {        // Q: [k8][rgrp][lane] float2 + j
                        off = base + ((size_t)(((D >> 3) * 8 + (loc >> 3)) * 32
                               + 4 * (loc & 7) + (D & 3)) << 1) + ((D >> 2) & 1);
                    } else if (sel == 1) { // K: [k4][nt][lane] float4 + c
                        off = base + ((size_t)(((D >> 4) * 8 + (loc >> 3)) * 32
                               + 4 * (loc & 7) + (D & 3)) << 2) + ((D >> 2) & 3);
                    } else {               // V: [k4][nt][lane] float4 + c (k from loc)
                        off = base + ((size_t)(((loc >> 4) * 8 + (D >> 3)) * 32
                               + 4 * (D & 7) + (loc & 3)) << 2) + ((loc >> 2) & 3);
                    }
                    dst[off] = vals[rr][dd];
                }
            }
        }
    }
}

// ============================================================================
// Kernel D: output projection (unchanged; 192 blocks, 2 CTA/SM).
// ============================================================================
__global__ __launch_bounds__(256, 2) void out_gemm(
    const float* __restrict__ W, const float* __restrict__ bias, float* __restrict__ out)
{
    extern __shared__ float sh[];
    const int m0 = blockIdx.x * 128, n0 = blockIdx.y * 128;

    float acc[4][4][4] = {};
    proj_core(g_ctx + (size_t)m0 * EMB, W + (size_t)n0 * EMB, acc, sh);

    const int tid = threadIdx.x, lane = tid & 31, wid = tid >> 5;
    const int g = lane >> 2, t = lane & 3;
    const int wy = wid >> 2, wx = wid & 3;
    #pragma unroll
    for (int mt = 0; mt < 4; mt++) {
        #pragma unroll
        for (int nt = 0; nt < 4; nt++) {
            int n = n0 + 32 * wx + 8 * nt + 2 * t;
            float bb0 = bias[n], bb1 = bias[n + 1];
            int row = m0 + 64 * wy + 16 * mt + g;
            *(float2*)&out[(size_t)row * EMB + n] =
                make_float2(acc[mt][nt][0] + bb0, acc[mt][nt][1] + bb1);
            *(float2*)&out[(size_t)(row + 8) * EMB + n] =
                make_float2(acc[mt][nt][2] + bb0, acc[mt][nt][3] + bb1);
        }
    }
}

// ============================================================================
// Kernel B v2: flash attention, fragment-major operands, Q in registers,
// K/V double-buffered, ONE barrier per kt.
// grid (16, 24), 256 thr, 2 CTA/SM.
// Smem: K 2 tiles (32KB) + V 2 tiles (32KB) + P (34KB) = 98KB.
// Per-kt: WAIT0 -> syncthreads -> issue prefetch(kt+1) -> QK/softmax/PV.
//  Hazards: reads(kt-1,buf b) < barrier(kt) < prefetch(kt+1,buf b)
//           < WAIT0(kt+1)+barrier(kt+1) < reads(kt+1,buf b).
// ============================================================================
#define PPAD 68
#define FLASH_SMEM ((4 * 4096 + 128 * PPAD) * 4)   // 100352 B

__global__ __launch_bounds__(256, 2) void flash_tc(float* __restrict__ wraw)
{
    extern __shared__ float sh[];
    float* Kb0 = sh;                  // K fragment tiles
    float* Kb1 = sh + 4096;
    float* Vb0 = sh + 8192;           // V fragment tiles
    float* Vb1 = sh + 12288;
    float* Ps  = sh + 16384;          // [128][PPAD] per-warp P tiles

    const int tid = threadIdx.x, lane = tid & 31, wid = tid >> 5;
    const int g = lane >> 2, t = lane & 3;
    const int hn = blockIdx.y;
    const int q0 = blockIdx.x * 128;

    const float* Qg = g_Qh + ((size_t)hn * 32 + 2 * blockIdx.x + (wid >> 2)) * 4096;
    const float* Kb = g_Kh + (size_t)hn * 32 * 4096;
    const float* Vb = g_Vh + (size_t)hn * 32 * 4096;

    // ---- Q fragments -> registers (loop-invariant; 16 coalesced LDG.64) ----
    const int wl2 = (wid & 3) * 2;
    float qa[8][4];                   // [k8][a0,a1,a2,a3] (tf32 bits as floats)
    #pragma unroll
    for (int k8 = 0; k8 < 8; k8++) {
        float2 r0 = *(const float2*)&Qg[((k8 * 8 + wl2) * 32 + lane) * 2];
        float2 r1 = *(const float2*)&Qg[((k8 * 8 + wl2 + 1) * 32 + lane) * 2];
        qa[k8][0] = r0.x; qa[k8][1] = r1.x; qa[k8][2] = r0.y; qa[k8][3] = r1.y;
    }

    // ---- stage K0, V0 into buffer 0 ----
    #pragma unroll
    for (int i = 0; i < 4; i++) {
        int idx = tid + 256 * i;
        cpa16(sm_addr(&Kb0[idx * 4]), Kb + (size_t)idx * 4);
        cpa16(sm_addr(&Vb0[idx * 4]), Vb + (size_t)idx * 4);
    }
    CP_COMMIT();

    float m0 = -INFINITY, m1 = -INFINITY, l0 = 0.f, l1 = 0.f;
    float oa[8][4] = {};
    const int qr = 16 * wid + g;
    float* Pw = Ps + wid * 16 * PPAD;

    for (int kt = 0; kt < 32; kt++) {
        CP_WAIT0();
        __syncthreads();              // buf[kt&1] landed+visible; kt-1 reads done
        const float* Kf = (kt & 1) ? Kb1 : Kb0;
        const float* Vf = (kt & 1) ? Vb1 : Vb0;
        if (kt + 1 < 32) {            // prefetch kt+1 into the other buffer
            float* Kd = (kt & 1) ? Kb0 : Kb1;
            float* Vd = (kt & 1) ? Vb0 : Vb1;
            const float* ks = Kb + (size_t)(kt + 1) * 4096;
            const float* vs = Vb + (size_t)(kt + 1) * 4096;
            #pragma unroll
            for (int i = 0; i < 4; i++) {
                int idx = tid + 256 * i;
                cpa16(sm_addr(&Kd[idx * 4]), ks + (size_t)idx * 4);
                cpa16(sm_addr(&Vd[idx * 4]), vs + (size_t)idx * 4);
            }
            CP_COMMIT();
        }

        // ---- S = Q @ K^T / 8 ----
        float sa[8][4] = {};
        #pragma unroll
        for (int k4 = 0; k4 < 4; k4++) {
            int k8a = 2 * k4, k8b = k8a + 1;
            unsigned A0a = __float_as_uint(qa[k8a][0]), A1a = __float_as_uint(qa[k8a][1]);
            unsigned A2a = __float_as_uint(qa[k8a][2]), A3a = __float_as_uint(qa[k8a][3]);
            unsigned A0b = __float_as_uint(qa[k8b][0]), A1b = __float_as_uint(qa[k8b][1]);
            unsigned A2b = __float_as_uint(qa[k8b][2]), A3b = __float_as_uint(qa[k8b][3]);
            #pragma unroll
            for (int nt = 0; nt < 8; nt++) {
                float4 kv = *(const float4*)&Kf[((k4 * 8 + nt) * 32 + lane) * 4];
                mma_tf(sa[nt], A0a, A1a, A2a, A3a,
                       __float_as_uint(kv.x), __float_as_uint(kv.y));
                mma_tf(sa[nt], A0b, A1b, A2b, A3b,
                       __float_as_uint(kv.z), __float_as_uint(kv.w));
            }
        }
        #pragma unroll
        for (int nt = 0; nt < 8; nt++) {
            sa[nt][0] *= 0.125f; sa[nt][1] *= 0.125f;
            sa[nt][2] *= 0.125f; sa[nt][3] *= 0.125f;
        }

        // ---- raw scores -> weights region (C layout: cols 2t,2t+1) ----
        if (wraw) {
            size_t rb0 = ((size_t)hn * S_LEN + (q0 + qr)) * S_LEN + (size_t)kt * 64 + 2 * t;
            #pragma unroll
            for (int nt = 0; nt < 8; nt++) {
                *(float2*)&wraw[rb0 + 8 * nt] = make_float2(sa[nt][0], sa[nt][1]);
                *(float2*)&wraw[rb0 + 8 * nt + 8 * (size_t)S_LEN] =
                    make_float2(sa[nt][2], sa[nt][3]);
            }
        }

        // ---- online softmax ----
        float lm0 = -INFINITY, lm1 = -INFINITY;
        #pragma unroll
        for (int nt = 0; nt < 8; nt++) {
            lm0 = fmaxf(lm0, fmaxf(sa[nt][0], sa[nt][1]));
            lm1 = fmaxf(lm1, fmaxf(sa[nt][2], sa[nt][3]));
        }
        lm0 = fmaxf(lm0, __shfl_xor_sync(0xffffffffu, lm0, 1));
        lm0 = fmaxf(lm0, __shfl_xor_sync(0xffffffffu, lm0, 2));
        lm1 = fmaxf(lm1, __shfl_xor_sync(0xffffffffu, lm1, 1));
        lm1 = fmaxf(lm1, __shfl_xor_sync(0xffffffffu, lm1, 2));
        float nm0 = fmaxf(m0, lm0), nm1 = fmaxf(m1, lm1);
        float ts0 = 0.f, ts1 = 0.f;
        #pragma unroll
        for (int nt = 0; nt < 8; nt++) {
            float p0 = __expf(sa[nt][0] - nm0);
            float p1 = __expf(sa[nt][1] - nm0);
            float p2 = __expf(sa[nt][2] - nm1);
            float p3 = __expf(sa[nt][3] - nm1);
            ts0 += p0 + p1; ts1 += p2 + p3;
            sa[nt][0] = f2tf_f(p0);
            sa[nt][1] = f2tf_f(p1);
            sa[nt][2] = f2tf_f(p2);
            sa[nt][3] = f2tf_f(p3);
        }
        ts0 += __shfl_xor_sync(0xffffffffu, ts0, 1);
        ts0 += __shfl_xor_sync(0xffffffffu, ts0, 2);
        ts1 += __shfl_xor_sync(0xffffffffu, ts1, 1);
        ts1 += __shfl_xor_sync(0xffffffffu, ts1, 2);
        float sc0 = __expf(m0 - nm0), sc1 = __expf(m1 - nm1);
        l0 = l0 * sc0 + ts0; l1 = l1 * sc1 + ts1;
        m0 = nm0; m1 = nm1;
        #pragma unroll
        for (int nt = 0; nt < 8; nt++) {
            oa[nt][0] *= sc0; oa[nt][1] *= sc0;
            oa[nt][2] *= sc1; oa[nt][3] *= sc1;
        }

        // ---- P: C-layout store to per-warp tile, A-layout reload ----
        #pragma unroll
        for (int nt = 0; nt < 8; nt++) {
            *(float2*)&Pw[g * PPAD + 8 * nt + 2 * t] =
                make_float2(sa[nt][0], sa[nt][1]);
            *(float2*)&Pw[(g + 8) * PPAD + 8 * nt + 2 * t] =
                make_float2(sa[nt][2], sa[nt][3]);
        }
        __syncwarp();

        // ---- O += P @ V ----
        #pragma unroll
        for (int k4 = 0; k4 < 4; k4++) {
            int k8a = 2 * k4, k8b = k8a + 1;
            int paA = g * PPAD + 8 * k8a;
            unsigned A0a = __float_as_uint(Pw[paA + t]);
            unsigned A1a = __float_as_uint(Pw[paA + 8 * PPAD + t]);
            unsigned A2a = __float_as_uint(Pw[paA + t + 4]);
            unsigned A3a = __float_as_uint(Pw[paA + t + 4 + 8 * PPAD]);
            int paB = g * PPAD + 8 * k8b;
            unsigned A0b = __float_as_uint(Pw[paB + t]);
            unsigned A1b = __float_as_uint(Pw[paB + 8 * PPAD + t]);
            unsigned A2b = __float_as_uint(Pw[paB + t + 4]);
            unsigned A3b = __float_as_uint(Pw[paB + t + 4 + 8 * PPAD]);
            #pragma unroll
            for (int nt = 0; nt < 8; nt++) {
                float4 vv = *(const float4*)&Vf[((k4 * 8 + nt) * 32 + lane) * 4];
                mma_tf(oa[nt], A0a, A1a, A2a, A3a,
                       __float_as_uint(vv.x), __float_as_uint(vv.y));
                mma_tf(oa[nt], A0b, A1b, A2b, A3b,
                       __float_as_uint(vv.z), __float_as_uint(vv.w));
            }
        }
        // no bottom barrier: next iteration's top barrier covers reuse
    }

    // epilogue: normalize, scatter ctx to [S,B,E], save (m,l) for norm kernel
    float inv0 = 1.f / l0, inv1 = 1.f / l1;
    const int r0 = q0 + qr, r1 = r0 + 8;
    const int bI = hn / NHEAD, hI = hn % NHEAD;
    #pragma unroll
    for (int nt = 0; nt < 8; nt++) {
        int d0 = 8 * nt + 2 * t;
        *(float2*)&g_ctx[((size_t)r0 * BATCH + bI) * EMB + hI * HD + d0] =
            make_float2(oa[nt][0] * inv0, oa[nt][1] * inv0);
        *(float2*)&g_ctx[((size_t)r1 * BATCH + bI) * EMB + hI * HD + d0] =
            make_float2(oa[nt][2] * inv1, oa[nt][3] * inv1);
    }
    if (t == 0) {
        g_m[hn * S_LEN + r0] = m0; g_m[hn * S_LEN + r1] = m1;
        g_l[hn * S_LEN + r0] = l0; g_l[hn * S_LEN + r1] = l1;
    }
}

// ============================================================================
// Kernel C: normalize raw scores in place: w = exp(s - m[row]) / l[row].
// Zero smem, full occupancy (measured ~134us, HBM roofline).
// ============================================================================
__global__ __launch_bounds__(256) void softmax_norm_kernel(float* __restrict__ w)
{
    size_t i4 = (size_t)blockIdx.x * blockDim.x + threadIdx.x;
    size_t row = i4 / (S_LEN / 4);
    float m = g_m[row];
    float inv = 1.f / g_l[row];
    float4* wv = (float4*)w + i4;
    float4 v = *wv;
    v.x = __expf(v.x - m) * inv;
    v.y = __expf(v.y - m) * inv;
    v.z = __expf(v.z - m) * inv;
    v.w = __expf(v.w - m) * inv;
    *wv = v;
}

// ============================================================================
extern "C" void kernel_launch(void* const* d_in, const int* in_sizes, int n_in,
                              void* d_out, int out_size)
{
    const float* q   = (const float*)d_in[0];
    const float* k   = (const float*)d_in[1];
    const float* v   = (const float*)d_in[2];
    const float* W_Q = (const float*)d_in[3];
    const float* W_K = (const float*)d_in[4];
    const float* W_V = (const float*)d_in[5];
    const float* b_Q = (const float*)d_in[6];
    const float* b_K = (const float*)d_in[7];
    const float* b_V = (const float*)d_in[8];
    const float* W_O = (const float*)d_in[9];
    const float* b_O = (const float*)d_in[10];
    float* out = (float*)d_out;

    const long long NW_LL = (long long)NH * S_LEN * S_LEN;  // 100663296
    const long long total = (long long)OUT0 + NW_LL;
    float* wraw = ((long long)out_size >= total) ? (out + OUT0) : nullptr;

    cudaFuncSetAttribute(qkv_gemm,
                         cudaFuncAttributeMaxDynamicSharedMemorySize, PROJ_SMEM);
    cudaFuncSetAttribute(out_gemm,
                         cudaFuncAttributeMaxDynamicSharedMemorySize, PROJ_SMEM);
    cudaFuncSetAttribute(flash_tc,
                         cudaFuncAttributeMaxDynamicSharedMemorySize, FLASH_SMEM);

    dim3 gQKV(M_ROWS / 128, EMB / 128, 3);   // 32 x 6 x 3
    qkv_gemm<<<gQKV, 256, PROJ_SMEM>>>(q, k, v, W_Q, W_K, W_V, b_Q, b_K, b_V);

    dim3 gB(S_LEN / 128, NH);                // 16 x 24
    flash_tc<<<gB, 256, FLASH_SMEM>>>(wraw);

    if (wraw) {
        long long n4 = NW_LL / 4;            // 25165824 float4s
        int blocks = (int)(n4 / 256);        // 98304
        softmax_norm_kernel<<<blocks, 256>>>(wraw);
    }

    dim3 gO(M_ROWS / 128, EMB / 128);        // 32 x 6
    out_gemm<<<gO, 256, PROJ_SMEM>>>(W_O, b_O, out);
}

// round 17
// speedup vs baseline: 1.5054x; 1.1596x over previous
#include <cuda_runtime.h>
#include <math.h>

// Problem constants
#define S_LEN  2048
#define BATCH  2
#define EMB    768
#define NHEAD  12
#define HD     64
#define NH     (BATCH*NHEAD)        // 24 flattened heads
#define M_ROWS (S_LEN*BATCH)        // 4096
#define OUT0   (S_LEN*BATCH*EMB)    // 3145728 floats (output tensor)

// ---------------- device scratch (static, allocation-free) ----------------
// Qh/Kh/Vh hold tf32-prerounded values in MMA-FRAGMENT-MAJOR tile layouts:
//  per (head, 64-row tile) of 4096 floats:
//   Q tile: [k8][rgrp][lane] float2 = {Q[8rgrp+g][8k8+t], Q[..][8k8+t+4]}
//   K tile: [k4][nt][lane] float4 = K[8nt+g][16k4 + t + {0,4,8,12}]
//   V tile: [k4][nt][lane] float4 = V[16k4 + t + {0,4,8,12}][8nt+g]
//  (lane = 4g+t; g=lane>>2, t=lane&3)
__device__ float g_Qh[NH * S_LEN * HD];
__device__ float g_Kh[NH * S_LEN * HD];
__device__ float g_Vh[NH * S_LEN * HD];
__device__ float g_ctx[M_ROWS * EMB];     // attn_output in [S,B,E] layout (full fp32)
__device__ float g_m[NH * S_LEN];         // per-row softmax max
__device__ float g_l[NH * S_LEN];         // per-row softmax sum

// ============================================================================
// portable (compute_103-safe) helpers
// tf32 m16n8k8 fragment layouts (PTX ISA):
//  A (16x8):  a0=(g, t)  a1=(g+8, t)  a2=(g, t+4)  a3=(g+8, t+4)
//  B (8x8):   b0=(k=t, n=g)  b1=(k=t+4, n=g)
//  C (16x8):  c0=(g, 2t) c1=(g, 2t+1) c2=(g+8, 2t) c3=(g+8, 2t+1)
// ============================================================================
__device__ __forceinline__ unsigned sm_addr(const void* p) {
    unsigned a;
    asm("{ .reg .u64 t; cvta.to.shared.u64 t, %1; cvt.u32.u64 %0, t; }" : "=r"(a) : "l"(p));
    return a;
}
__device__ __forceinline__ unsigned f2tf(float x) {
    unsigned r;
    asm("cvt.rna.tf32.f32 %0, %1;" : "=r"(r) : "f"(x));
    return r;
}
__device__ __forceinline__ float f2tf_f(float x) { return __uint_as_float(f2tf(x)); }

__device__ __forceinline__ void mma_tf(float c[4], unsigned a0, unsigned a1,
                                       unsigned a2, unsigned a3,
                                       unsigned b0, unsigned b1) {
    asm volatile(
        "mma.sync.aligned.m16n8k8.row.col.f32.tf32.tf32.f32 "
        "{%0,%1,%2,%3}, {%4,%5,%6,%7}, {%8,%9}, {%0,%1,%2,%3};"
        : "+f"(c[0]), "+f"(c[1]), "+f"(c[2]), "+f"(c[3])
        : "r"(a0), "r"(a1), "r"(a2), "r"(a3), "r"(b0), "r"(b1));
}
__device__ __forceinline__ void cpa16(unsigned saddr, const void* gptr) {
    asm volatile("cp.async.cg.shared.global [%0], [%1], 16;" :: "r"(saddr), "l"(gptr));
}
#define CP_COMMIT()  asm volatile("cp.async.commit_group;")
#define CP_WAIT0()   asm volatile("cp.async.wait_group 0;")
#define CP_WAIT1()   asm volatile("cp.async.wait_group 1;")

// ============================================================================
// Projection GEMM core (unchanged): 3-stage cp.async pipeline, in-smem tf32
// conversion. C[128x128] = A[128x768] @ B[128x768]^T.
// ============================================================================
#define PLD 36
#define PBUF (128 * PLD)
#define PROJ_SMEM (6 * PBUF * 4)         // 110592 B

__device__ __forceinline__ void proj_core(const float* __restrict__ Ag,
                                          const float* __restrict__ Bg,
                                          float (&acc)[4][4][4], float* sh)
{
    float* Ab[3] = { sh,            sh + PBUF,     sh + 2 * PBUF };
    float* Bb[3] = { sh + 3 * PBUF, sh + 4 * PBUF, sh + 5 * PBUF };
    const int tid = threadIdx.x;
    const int lane = tid & 31, wid = tid >> 5;
    const int g = lane >> 2, t = lane & 3;
    const int wy = wid >> 2, wx = wid & 3;

    auto stage = [&](int c, int bs) {
        #pragma unroll
        for (int i = 0; i < 4; i++) {
            int idx = tid + 256 * i;
            int row = idx >> 3, c4 = (idx & 7) * 4;
            cpa16(sm_addr(&Ab[bs][row * PLD + c4]), Ag + (size_t)row * EMB + c * 32 + c4);
            cpa16(sm_addr(&Bb[bs][row * PLD + c4]), Bg + (size_t)row * EMB + c * 32 + c4);
        }
        CP_COMMIT();
    };
    auto convert = [&](int bs) {
        #pragma unroll
        for (int i = 0; i < 4; i++) {
            int idx = tid + 256 * i;
            int row = idx >> 3, c4 = (idx & 7) * 4;
            float4* pa = (float4*)&Ab[bs][row * PLD + c4];
            float4 va = *pa;
            va.x = f2tf_f(va.x); va.y = f2tf_f(va.y);
            va.z = f2tf_f(va.z); va.w = f2tf_f(va.w);
            *pa = va;
            float4* pb = (float4*)&Bb[bs][row * PLD + c4];
            float4 vb = *pb;
            vb.x = f2tf_f(vb.x); vb.y = f2tf_f(vb.y);
            vb.z = f2tf_f(vb.z); vb.w = f2tf_f(vb.w);
            *pb = vb;
        }
    };

    stage(0, 0);
    stage(1, 1);
    for (int c = 0; c < 24; c++) {
        if (c < 23) { CP_WAIT1(); } else { CP_WAIT0(); }
        __syncthreads();
        convert(c % 3);
        __syncthreads();

        const float* Af = Ab[c % 3];
        const float* Bf = Bb[c % 3];
        #pragma unroll
        for (int ks = 0; ks < 4; ks++) {
            const int k0s = 8 * ks;
            unsigned a[4][4];
            #pragma unroll
            for (int mt = 0; mt < 4; mt++) {
                int ra = (64 * wy + 16 * mt + g) * PLD + k0s;
                a[mt][0] = __float_as_uint(Af[ra + t]);
                a[mt][1] = __float_as_uint(Af[ra + 8 * PLD + t]);
                a[mt][2] = __float_as_uint(Af[ra + t + 4]);
                a[mt][3] = __float_as_uint(Af[ra + 8 * PLD + t + 4]);
            }
            #pragma unroll
            for (int nt = 0; nt < 4; nt++) {
                int rb = (32 * wx + 8 * nt + g) * PLD + k0s;
                unsigned b0 = __float_as_uint(Bf[rb + t]);
                unsigned b1 = __float_as_uint(Bf[rb + t + 4]);
                #pragma unroll
                for (int mt = 0; mt < 4; mt++)
                    mma_tf(acc[mt][nt], a[mt][0], a[mt][1], a[mt][2], a[mt][3], b0, b1);
            }
        }
        if (c + 2 < 24) stage(c + 2, (c + 2) % 3);
    }
}

// ============================================================================
// Kernel A: fused QKV projection; epilogue scatters tf32-prerounded values
// into the FRAGMENT-MAJOR tile layouts consumed by flash/weights.
// ============================================================================
__global__ __launch_bounds__(256, 2) void qkv_gemm(
    const float* __restrict__ q, const float* __restrict__ k, const float* __restrict__ v,
    const float* __restrict__ WQ, const float* __restrict__ WK, const float* __restrict__ WV,
    const float* __restrict__ bQ, const float* __restrict__ bK, const float* __restrict__ bV)
{
    extern __shared__ float sh[];
    const int m0 = blockIdx.x * 128, n0 = blockIdx.y * 128, sel = blockIdx.z;
    const float* X    = (sel == 0) ? q  : (sel == 1) ? k  : v;
    const float* W    = (sel == 0) ? WQ : (sel == 1) ? WK : WV;
    const float* bias = (sel == 0) ? bQ : (sel == 1) ? bK : bV;
    float* dst        = (sel == 0) ? g_Qh : (sel == 1) ? g_Kh : g_Vh;

    float acc[4][4][4] = {};
    proj_core(X + (size_t)m0 * EMB, W + (size_t)n0 * EMB, acc, sh);

    const int tid = threadIdx.x, lane = tid & 31, wid = tid >> 5;
    const int g = lane >> 2, t = lane & 3;
    const int wy = wid >> 2, wx = wid & 3;

    #pragma unroll
    for (int mt = 0; mt < 4; mt++) {
        #pragma unroll
        for (int nt = 0; nt < 4; nt++) {
            int n = n0 + 32 * wx + 8 * nt + 2 * t;    // cols n, n+1
            int h = n >> 6;
            int row = m0 + 64 * wy + 16 * mt + g;     // rows row, row+8
            float bb0 = bias[n], bb1 = bias[n + 1];
            float vals[2][2] = {
                { f2tf_f(acc[mt][nt][0] + bb0), f2tf_f(acc[mt][nt][1] + bb1) },
                { f2tf_f(acc[mt][nt][2] + bb0), f2tf_f(acc[mt][nt][3] + bb1) } };
            #pragma unroll
            for (int rr = 0; rr < 2; rr++) {
                int R = row + 8 * rr;
                int s = R >> 1, bI = R & 1;
                int hn = bI * NHEAD + h;
                int t64 = s >> 6, loc = s & 63;
                size_t base = ((size_t)hn * 32 + t64) * 4096;
                #pragma unroll
                for (int dd = 0; dd < 2; dd++) {
                    int D = (n & 63) + dd;
                    size_t off;
                    if (sel == 0) {        // Q: [k8][rgrp][lane] float2 + j
                        off = base + ((size_t)(((D >> 3) * 8 + (loc >> 3)) * 32
                               + 4 * (loc & 7) + (D & 3)) << 1) + ((D >> 2) & 1);
                    } else if (sel == 1) { // K: [k4][nt][lane] float4 + c
                        off = base + ((size_t)(((D >> 4) * 8 + (loc >> 3)) * 32
                               + 4 * (loc & 7) + (D & 3)) << 2) + ((D >> 2) & 3);
                    } else {               // V: [k4][nt][lane] float4 + c (k from loc)
                        off = base + ((size_t)(((loc >> 4) * 8 + (D >> 3)) * 32
                               + 4 * (D & 7) + (loc & 3)) << 2) + ((loc >> 2) & 3);
                    }
                    dst[off] = vals[rr][dd];
                }
            }
        }
    }
}

// ============================================================================
// Kernel D: output projection (unchanged; 192 blocks, 2 CTA/SM).
// ============================================================================
__global__ __launch_bounds__(256, 2) void out_gemm(
    const float* __restrict__ W, const float* __restrict__ bias, float* __restrict__ out)
{
    extern __shared__ float sh[];
    const int m0 = blockIdx.x * 128, n0 = blockIdx.y * 128;

    float acc[4][4][4] = {};
    proj_core(g_ctx + (size_t)m0 * EMB, W + (size_t)n0 * EMB, acc, sh);

    const int tid = threadIdx.x, lane = tid & 31, wid = tid >> 5;
    const int g = lane >> 2, t = lane & 3;
    const int wy = wid >> 2, wx = wid & 3;
    #pragma unroll
    for (int mt = 0; mt < 4; mt++) {
        #pragma unroll
        for (int nt = 0; nt < 4; nt++) {
            int n = n0 + 32 * wx + 8 * nt + 2 * t;
            float bb0 = bias[n], bb1 = bias[n + 1];
            int row = m0 + 64 * wy + 16 * mt + g;
            *(float2*)&out[(size_t)row * EMB + n] =
                make_float2(acc[mt][nt][0] + bb0, acc[mt][nt][1] + bb1);
            *(float2*)&out[(size_t)(row + 8) * EMB + n] =
                make_float2(acc[mt][nt][2] + bb0, acc[mt][nt][3] + bb1);
        }
    }
}

// ============================================================================
// Kernel B v3: flash attention WITHOUT weight stores (m/l + ctx only).
// Fragment-major operands, Q in registers, K/V double-buffered, 1 barrier/kt.
// grid (16, 24), 256 thr, 2 CTA/SM. Smem: K 2 + V 2 tiles + P = 98KB.
// ============================================================================
#define PPAD 68
#define FLASH_SMEM ((4 * 4096 + 128 * PPAD) * 4)   // 100352 B

__global__ __launch_bounds__(256, 2) void flash_tc()
{
    extern __shared__ float sh[];
    float* Kb0 = sh;
    float* Kb1 = sh + 4096;
    float* Vb0 = sh + 8192;
    float* Vb1 = sh + 12288;
    float* Ps  = sh + 16384;          // [128][PPAD] per-warp P tiles

    const int tid = threadIdx.x, lane = tid & 31, wid = tid >> 5;
    const int g = lane >> 2, t = lane & 3;
    const int hn = blockIdx.y;
    const int q0 = blockIdx.x * 128;

    const float* Qg = g_Qh + ((size_t)hn * 32 + 2 * blockIdx.x + (wid >> 2)) * 4096;
    const float* Kb = g_Kh + (size_t)hn * 32 * 4096;
    const float* Vb = g_Vh + (size_t)hn * 32 * 4096;

    // ---- Q fragments -> registers (loop-invariant) ----
    const int wl2 = (wid & 3) * 2;
    float qa[8][4];
    #pragma unroll
    for (int k8 = 0; k8 < 8; k8++) {
        float2 r0 = *(const float2*)&Qg[((k8 * 8 + wl2) * 32 + lane) * 2];
        float2 r1 = *(const float2*)&Qg[((k8 * 8 + wl2 + 1) * 32 + lane) * 2];
        qa[k8][0] = r0.x; qa[k8][1] = r1.x; qa[k8][2] = r0.y; qa[k8][3] = r1.y;
    }

    #pragma unroll
    for (int i = 0; i < 4; i++) {
        int idx = tid + 256 * i;
        cpa16(sm_addr(&Kb0[idx * 4]), Kb + (size_t)idx * 4);
        cpa16(sm_addr(&Vb0[idx * 4]), Vb + (size_t)idx * 4);
    }
    CP_COMMIT();

    float m0 = -INFINITY, m1 = -INFINITY, l0 = 0.f, l1 = 0.f;
    float oa[8][4] = {};
    const int qr = 16 * wid + g;
    float* Pw = Ps + wid * 16 * PPAD;

    for (int kt = 0; kt < 32; kt++) {
        CP_WAIT0();
        __syncthreads();
        const float* Kf = (kt & 1) ? Kb1 : Kb0;
        const float* Vf = (kt & 1) ? Vb1 : Vb0;
        if (kt + 1 < 32) {
            float* Kd = (kt & 1) ? Kb0 : Kb1;
            float* Vd = (kt & 1) ? Vb0 : Vb1;
            const float* ks = Kb + (size_t)(kt + 1) * 4096;
            const float* vs = Vb + (size_t)(kt + 1) * 4096;
            #pragma unroll
            for (int i = 0; i < 4; i++) {
                int idx = tid + 256 * i;
                cpa16(sm_addr(&Kd[idx * 4]), ks + (size_t)idx * 4);
                cpa16(sm_addr(&Vd[idx * 4]), vs + (size_t)idx * 4);
            }
            CP_COMMIT();
        }

        // ---- S = Q @ K^T / 8 ----
        float sa[8][4] = {};
        #pragma unroll
        for (int k4 = 0; k4 < 4; k4++) {
            int k8a = 2 * k4, k8b = k8a + 1;
            unsigned A0a = __float_as_uint(qa[k8a][0]), A1a = __float_as_uint(qa[k8a][1]);
            unsigned A2a = __float_as_uint(qa[k8a][2]), A3a = __float_as_uint(qa[k8a][3]);
            unsigned A0b = __float_as_uint(qa[k8b][0]), A1b = __float_as_uint(qa[k8b][1]);
            unsigned A2b = __float_as_uint(qa[k8b][2]), A3b = __float_as_uint(qa[k8b][3]);
            #pragma unroll
            for (int nt = 0; nt < 8; nt++) {
                float4 kv = *(const float4*)&Kf[((k4 * 8 + nt) * 32 + lane) * 4];
                mma_tf(sa[nt], A0a, A1a, A2a, A3a,
                       __float_as_uint(kv.x), __float_as_uint(kv.y));
                mma_tf(sa[nt], A0b, A1b, A2b, A3b,
                       __float_as_uint(kv.z), __float_as_uint(kv.w));
            }
        }
        #pragma unroll
        for (int nt = 0; nt < 8; nt++) {
            sa[nt][0] *= 0.125f; sa[nt][1] *= 0.125f;
            sa[nt][2] *= 0.125f; sa[nt][3] *= 0.125f;
        }

        // ---- online softmax ----
        float lm0 = -INFINITY, lm1 = -INFINITY;
        #pragma unroll
        for (int nt = 0; nt < 8; nt++) {
            lm0 = fmaxf(lm0, fmaxf(sa[nt][0], sa[nt][1]));
            lm1 = fmaxf(lm1, fmaxf(sa[nt][2], sa[nt][3]));
        }
        lm0 = fmaxf(lm0, __shfl_xor_sync(0xffffffffu, lm0, 1));
        lm0 = fmaxf(lm0, __shfl_xor_sync(0xffffffffu, lm0, 2));
        lm1 = fmaxf(lm1, __shfl_xor_sync(0xffffffffu, lm1, 1));
        lm1 = fmaxf(lm1, __shfl_xor_sync(0xffffffffu, lm1, 2));
        float nm0 = fmaxf(m0, lm0), nm1 = fmaxf(m1, lm1);
        float ts0 = 0.f, ts1 = 0.f;
        #pragma unroll
        for (int nt = 0; nt < 8; nt++) {
            float p0 = __expf(sa[nt][0] - nm0);
            float p1 = __expf(sa[nt][1] - nm0);
            float p2 = __expf(sa[nt][2] - nm1);
            float p3 = __expf(sa[nt][3] - nm1);
            ts0 += p0 + p1; ts1 += p2 + p3;
            sa[nt][0] = f2tf_f(p0);
            sa[nt][1] = f2tf_f(p1);
            sa[nt][2] = f2tf_f(p2);
            sa[nt][3] = f2tf_f(p3);
        }
        ts0 += __shfl_xor_sync(0xffffffffu, ts0, 1);
        ts0 += __shfl_xor_sync(0xffffffffu, ts0, 2);
        ts1 += __shfl_xor_sync(0xffffffffu, ts1, 1);
        ts1 += __shfl_xor_sync(0xffffffffu, ts1, 2);
        float sc0 = __expf(m0 - nm0), sc1 = __expf(m1 - nm1);
        l0 = l0 * sc0 + ts0; l1 = l1 * sc1 + ts1;
        m0 = nm0; m1 = nm1;
        #pragma unroll
        for (int nt = 0; nt < 8; nt++) {
            oa[nt][0] *= sc0; oa[nt][1] *= sc0;
            oa[nt][2] *= sc1; oa[nt][3] *= sc1;
        }

        // ---- P: C-layout store to per-warp tile, A-layout reload ----
        #pragma unroll
        for (int nt = 0; nt < 8; nt++) {
            *(float2*)&Pw[g * PPAD + 8 * nt + 2 * t] =
                make_float2(sa[nt][0], sa[nt][1]);
            *(float2*)&Pw[(g + 8) * PPAD + 8 * nt + 2 * t] =
                make_float2(sa[nt][2], sa[nt][3]);
        }
        __syncwarp();

        // ---- O += P @ V ----
        #pragma unroll
        for (int k4 = 0; k4 < 4; k4++) {
            int k8a = 2 * k4, k8b = k8a + 1;
            int paA = g * PPAD + 8 * k8a;
            unsigned A0a = __float_as_uint(Pw[paA + t]);
            unsigned A1a = __float_as_uint(Pw[paA + 8 * PPAD + t]);
            unsigned A2a = __float_as_uint(Pw[paA + t + 4]);
            unsigned A3a = __float_as_uint(Pw[paA + t + 4 + 8 * PPAD]);
            int paB = g * PPAD + 8 * k8b;
            unsigned A0b = __float_as_uint(Pw[paB + t]);
            unsigned A1b = __float_as_uint(Pw[paB + 8 * PPAD + t]);
            unsigned A2b = __float_as_uint(Pw[paB + t + 4]);
            unsigned A3b = __float_as_uint(Pw[paB + t + 4 + 8 * PPAD]);
            #pragma unroll
            for (int nt = 0; nt < 8; nt++) {
                float4 vv = *(const float4*)&Vf[((k4 * 8 + nt) * 32 + lane) * 4];
                mma_tf(oa[nt], A0a, A1a, A2a, A3a,
                       __float_as_uint(vv.x), __float_as_uint(vv.y));
                mma_tf(oa[nt], A0b, A1b, A2b, A3b,
                       __float_as_uint(vv.z), __float_as_uint(vv.w));
            }
        }
    }

    // epilogue: normalize, scatter ctx to [S,B,E], save (m,l)
    float inv0 = 1.f / l0, inv1 = 1.f / l1;
    const int r0 = q0 + qr, r1 = r0 + 8;
    const int bI = hn / NHEAD, hI = hn % NHEAD;
    #pragma unroll
    for (int nt = 0; nt < 8; nt++) {
        int d0 = 8 * nt + 2 * t;
        *(float2*)&g_ctx[((size_t)r0 * BATCH + bI) * EMB + hI * HD + d0] =
            make_float2(oa[nt][0] * inv0, oa[nt][1] * inv0);
        *(float2*)&g_ctx[((size_t)r1 * BATCH + bI) * EMB + hI * HD + d0] =
            make_float2(oa[nt][2] * inv1, oa[nt][3] * inv1);
    }
    if (t == 0) {
        g_m[hn * S_LEN + r0] = m0; g_m[hn * S_LEN + r1] = m1;
        g_l[hn * S_LEN + r0] = l0; g_l[hn * S_LEN + r1] = l1;
    }
}

// ============================================================================
// Kernel W: recompute QK^T (byte-identical mma sequence to flash) and write
// NORMALIZED weights directly: w = exp(s - m)/l. Pure 402MB stream of stores
// (replaces the 805MB read-modify-write normalize pass).
// grid (16, 24), 256 thr; smem 32KB (K double buffer) -> high occupancy.
// ============================================================================
#define WT_SMEM (2 * 4096 * 4)   // 32768 B

__global__ __launch_bounds__(256) void weights_kernel(float* __restrict__ w)
{
    extern __shared__ float sh[];
    float* Kb0 = sh;
    float* Kb1 = sh + 4096;

    const int tid = threadIdx.x, lane = tid & 31, wid = tid >> 5;
    const int g = lane >> 2, t = lane & 3;
    const int hn = blockIdx.y;
    const int q0 = blockIdx.x * 128;

    const float* Qg = g_Qh + ((size_t)hn * 32 + 2 * blockIdx.x + (wid >> 2)) * 4096;
    const float* Kb = g_Kh + (size_t)hn * 32 * 4096;

    // Q fragments -> registers (same as flash)
    const int wl2 = (wid & 3) * 2;
    float qa[8][4];
    #pragma unroll
    for (int k8 = 0; k8 < 8; k8++) {
        float2 r0 = *(const float2*)&Qg[((k8 * 8 + wl2) * 32 + lane) * 2];
        float2 r1 = *(const float2*)&Qg[((k8 * 8 + wl2 + 1) * 32 + lane) * 2];
        qa[k8][0] = r0.x; qa[k8][1] = r1.x; qa[k8][2] = r0.y; qa[k8][3] = r1.y;
    }

    // per-row m and 1/l (rows q0+qr and q0+qr+8)
    const int qr = 16 * wid + g;
    float m0 = g_m[hn * S_LEN + q0 + qr];
    float m1 = g_m[hn * S_LEN + q0 + qr + 8];
    float inv0 = 1.f / g_l[hn * S_LEN + q0 + qr];
    float inv1 = 1.f / g_l[hn * S_LEN + q0 + qr + 8];

    #pragma unroll
    for (int i = 0; i < 4; i++) {
        int idx = tid + 256 * i;
        cpa16(sm_addr(&Kb0[idx * 4]), Kb + (size_t)idx * 4);
    }
    CP_COMMIT();

    for (int kt = 0; kt < 32; kt++) {
        CP_WAIT0();
        __syncthreads();
        const float* Kf = (kt & 1) ? Kb1 : Kb0;
        if (kt + 1 < 32) {
            float* Kd = (kt & 1) ? Kb0 : Kb1;
            const float* ks = Kb + (size_t)(kt + 1) * 4096;
            #pragma unroll
            for (int i = 0; i < 4; i++) {
                int idx = tid + 256 * i;
                cpa16(sm_addr(&Kd[idx * 4]), ks + (size_t)idx * 4);
            }
            CP_COMMIT();
        }

        // ---- S = Q @ K^T (IDENTICAL mma sequence to flash) ----
        float sa[8][4] = {};
        #pragma unroll
        for (int k4 = 0; k4 < 4; k4++) {
            int k8a = 2 * k4, k8b = k8a + 1;
            unsigned A0a = __float_as_uint(qa[k8a][0]), A1a = __float_as_uint(qa[k8a][1]);
            unsigned A2a = __float_as_uint(qa[k8a][2]), A3a = __float_as_uint(qa[k8a][3]);
            unsigned A0b = __float_as_uint(qa[k8b][0]), A1b = __float_as_uint(qa[k8b][1]);
            unsigned A2b = __float_as_uint(qa[k8b][2]), A3b = __float_as_uint(qa[k8b][3]);
            #pragma unroll
            for (int nt = 0; nt < 8; nt++) {
                float4 kv = *(const float4*)&Kf[((k4 * 8 + nt) * 32 + lane) * 4];
                mma_tf(sa[nt], A0a, A1a, A2a, A3a,
                       __float_as_uint(kv.x), __float_as_uint(kv.y));
                mma_tf(sa[nt], A0b, A1b, A2b, A3b,
                       __float_as_uint(kv.z), __float_as_uint(kv.w));
            }
        }

        // ---- w = exp(s/8 - m) * (1/l), written directly (C layout) ----
        size_t rb0 = ((size_t)hn * S_LEN + (q0 + qr)) * S_LEN + (size_t)kt * 64 + 2 * t;
        #pragma unroll
        for (int nt = 0; nt < 8; nt++) {
            float s0 = sa[nt][0] * 0.125f, s1 = sa[nt][1] * 0.125f;
            float s2 = sa[nt][2] * 0.125f, s3 = sa[nt][3] * 0.125f;
            *(float2*)&w[rb0 + 8 * nt] =
                make_float2(__expf(s0 - m0) * inv0, __expf(s1 - m0) * inv0);
            *(float2*)&w[rb0 + 8 * nt + 8 * (size_t)S_LEN] =
                make_float2(__expf(s2 - m1) * inv1, __expf(s3 - m1) * inv1);
        }
    }
}

// ============================================================================
extern "C" void kernel_launch(void* const* d_in, const int* in_sizes, int n_in,
                              void* d_out, int out_size)
{
    const float* q   = (const float*)d_in[0];
    const float* k   = (const float*)d_in[1];
    const float* v   = (const float*)d_in[2];
    const float* W_Q = (const float*)d_in[3];
    const float* W_K = (const float*)d_in[4];
    const float* W_V = (const float*)d_in[5];
    const float* b_Q = (const float*)d_in[6];
    const float* b_K = (const float*)d_in[7];
    const float* b_V = (const float*)d_in[8];
    const float* W_O = (const float*)d_in[9];
    const float* b_O = (const float*)d_in[10];
    float* out = (float*)d_out;

    const long long NW_LL = (long long)NH * S_LEN * S_LEN;  // 100663296
    const long long total = (long long)OUT0 + NW_LL;
    float* wraw = ((long long)out_size >= total) ? (out + OUT0) : nullptr;

    cudaFuncSetAttribute(qkv_gemm,
                         cudaFuncAttributeMaxDynamicSharedMemorySize, PROJ_SMEM);
    cudaFuncSetAttribute(out_gemm,
                         cudaFuncAttributeMaxDynamicSharedMemorySize, PROJ_SMEM);
    cudaFuncSetAttribute(flash_tc,
                         cudaFuncAttributeMaxDynamicSharedMemorySize, FLASH_SMEM);

    dim3 gQKV(M_ROWS / 128, EMB / 128, 3);   // 32 x 6 x 3
    qkv_gemm<<<gQKV, 256, PROJ_SMEM>>>(q, k, v, W_Q, W_K, W_V, b_Q, b_K, b_V);

    dim3 gB(S_LEN / 128, NH);                // 16 x 24
    flash_tc<<<gB, 256, FLASH_SMEM>>>();

    if (wraw) {
        weights_kernel<<<gB, 256, WT_SMEM>>>(wraw);
    }

    dim3 gO(M_ROWS / 128, EMB / 128);        // 32 x 6
    out_gemm<<<gO, 256, PROJ_SMEM>>>(W_O, b_O, out);
}